// round 14
// baseline (speedup 1.0000x reference)
#include <cuda_runtime.h>
#include <cuda_bf16.h>
#include <cstdint>

#define Bc 512
#define Tc 256
#define Vc 128
#define Ec 64
#define Hc 64
#define Gc 256  // 4*H
#define Mb 4    // batches per LSTM CTA

// ---------------- scratch (static device globals; no allocation) ----------------
__device__ __nv_bfloat16 g_x0b [(size_t)Bc*Tc*Ec];
__device__ float g_pre_f[(size_t)Bc*Tc*Gc];
__device__ float g_pre_b[(size_t)Bc*Tc*Gc];
__device__ __nv_bfloat16 g_hs0b[(size_t)Bc*Tc*2*Hc];
__device__ __nv_bfloat16 g_hs1b[(size_t)Bc*Tc*2*Hc];
__device__ float g_eem  [(size_t)Bc*Tc*Vc];
__device__ float g_emmax[Bc*Tc];
__device__ float g_MexpT[Vc*Vc];
__device__ int   g_len  [Bc];
__device__ float g_scorev[Bc];
__device__ float g_part [Bc];
__device__ float g_dummy[(size_t)Bc*Tc*Vc];   // unused out target for emissions
// bf16 weights
__device__ __nv_bfloat16 g_wih0f[Gc*Ec];
__device__ __nv_bfloat16 g_wih0b[Gc*Ec];
__device__ __nv_bfloat16 g_wih1f[Gc*2*Hc];
__device__ __nv_bfloat16 g_wih1b[Gc*2*Hc];
__device__ __nv_bfloat16 g_linwb[Vc*2*Hc];

// ---------------- helpers ----------------
__device__ __forceinline__ uint32_t smem_u32(const void* p) {
    uint32_t a;
    asm("{ .reg .u64 t; cvta.to.shared.u64 t, %1; cvt.u32.u64 %0, t; }" : "=r"(a) : "l"(p));
    return a;
}
__device__ __forceinline__ unsigned long long pk2(float x, float y) {
    unsigned long long r;
    asm("mov.b64 %0, {%1, %2};" : "=l"(r) : "f"(x), "f"(y));
    return r;
}
__device__ __forceinline__ unsigned long long ffma2(unsigned long long a,
                                                    unsigned long long b,
                                                    unsigned long long c) {
    unsigned long long d;
    asm("fma.rn.f32x2 %0, %1, %2, %3;" : "=l"(d) : "l"(a), "l"(b), "l"(c));
    return d;
}
__device__ __forceinline__ float2 unpk(unsigned long long v) {
    float2 r;
    asm("mov.b64 {%0, %1}, %2;" : "=f"(r.x), "=f"(r.y) : "l"(v));
    return r;
}
__device__ __forceinline__ float tanh_hw(float x) {
    float r;
    asm("tanh.approx.f32 %0, %1;" : "=f"(r) : "f"(x));
    return r;
}
__device__ __forceinline__ float sigmoid_hw(float x) {
    return fmaf(0.5f, tanh_hw(0.5f * x), 0.5f);
}
__device__ __forceinline__ void ldmx4(uint32_t* r, uint32_t addr) {
    asm volatile("ldmatrix.sync.aligned.m8n8.x4.shared.b16 {%0,%1,%2,%3}, [%4];"
                 : "=r"(r[0]), "=r"(r[1]), "=r"(r[2]), "=r"(r[3]) : "r"(addr));
}
__device__ __forceinline__ void mma16816(float* c, const uint32_t* a, uint32_t b0, uint32_t b1) {
    asm volatile(
        "mma.sync.aligned.m16n8k16.row.col.f32.bf16.bf16.f32 "
        "{%0,%1,%2,%3}, {%4,%5,%6,%7}, {%8,%9}, {%0,%1,%2,%3};"
        : "+f"(c[0]), "+f"(c[1]), "+f"(c[2]), "+f"(c[3])
        : "r"(a[0]), "r"(a[1]), "r"(a[2]), "r"(a[3]), "r"(b0), "r"(b1));
}

// ---------------- fused weight fp32 -> bf16 (all 5 weights) ----------------
__global__ void k_cvt5(const float* __restrict__ s0, const float* __restrict__ s1,
                       const float* __restrict__ s2, const float* __restrict__ s3,
                       const float* __restrict__ s4) {
    int i = blockIdx.x * blockDim.x + threadIdx.x;
    if (i < 16384)            g_wih0f[i] = __float2bfloat16(s0[i]);
    else if (i < 32768)       g_wih0b[i - 16384] = __float2bfloat16(s1[i - 16384]);
    else if (i < 65536)       g_wih1f[i - 32768] = __float2bfloat16(s2[i - 32768]);
    else if (i < 98304)       g_wih1b[i - 65536] = __float2bfloat16(s3[i - 65536]);
    else if (i < 114688)      g_linwb[i - 98304] = __float2bfloat16(s4[i - 98304]);
}

// ---------------- embedding gather (bf16 out, 8 elems/thread) ----------------
__global__ void k_embed(const int* __restrict__ x, const float* __restrict__ emb) {
    size_t i = (size_t)blockIdx.x * blockDim.x + threadIdx.x;
    if (i >= (size_t)Bc * Tc * Ec / 8) return;
    size_t n = i >> 3;
    int   e = (int)(i & 7) * 8;
    const float4* src = (const float4*)(emb + (size_t)x[n] * Ec + e);
    float4 v0 = src[0], v1 = src[1];
    __nv_bfloat16 o[8];
    o[0] = __float2bfloat16(v0.x); o[1] = __float2bfloat16(v0.y);
    o[2] = __float2bfloat16(v0.z); o[3] = __float2bfloat16(v0.w);
    o[4] = __float2bfloat16(v1.x); o[5] = __float2bfloat16(v1.y);
    o[6] = __float2bfloat16(v1.z); o[7] = __float2bfloat16(v1.w);
    *(uint4*)(g_x0b + i * 8) = *(uint4*)o;
}

// ---------------- HMMA GEMM: out[r, n] = sum_k A[r,k]*W[n,k] + bias ----------------
// blockIdx.z selects the (W, bias, out) set. EMEXP: write only eem/emmax (no out store).
template <int K, bool EMEXP>
__global__ __launch_bounds__(256) void k_mma(const __nv_bfloat16* __restrict__ A,
                                             const __nv_bfloat16* __restrict__ Wf,
                                             const __nv_bfloat16* __restrict__ Wb,
                                             const float* __restrict__ b1f,
                                             const float* __restrict__ b1b,
                                             const float* __restrict__ b2f,
                                             const float* __restrict__ b2b,
                                             float* __restrict__ outf,
                                             float* __restrict__ outb, int Gout) {
    constexpr int VPR   = K / 8;
    constexpr int TILEB = 128 * K * 2;
    constexpr int NKS   = K / 16;

    extern __shared__ char sm[];
    __shared__ float bias[128];
    __shared__ float smp[128][4];

    const __nv_bfloat16* W = blockIdx.z ? Wb : Wf;
    const float* b1 = blockIdx.z ? b1b : b1f;
    const float* b2 = blockIdx.z ? b2b : b2f;
    float* out = blockIdx.z ? outb : outf;

    uint32_t sA = smem_u32(sm);
    uint32_t sB = sA + TILEB;

    int tid = threadIdx.x, wid = tid >> 5, lane = tid & 31;
    size_t row0 = (size_t)blockIdx.x * 128;
    int    col0 = blockIdx.y * 128;

    if (tid < 128) bias[tid] = b1[col0 + tid] + (b2 ? b2[col0 + tid] : 0.f);

    {
        const uint4* Ag = (const uint4*)(A + row0 * K);
        const uint4* Wg = (const uint4*)(W + (size_t)col0 * K);
        char* smc = sm;
#pragma unroll 4
        for (int v = tid; v < 128 * VPR; v += 256) {
            int row = v / VPR, ck = v % VPR;
            int swb = ((ck & ~7) | ((ck ^ row) & 7)) * 16;
            *(uint4*)(smc + row * (2 * K) + swb) = Ag[v];
        }
#pragma unroll 4
        for (int v = tid; v < 128 * VPR; v += 256) {
            int row = v / VPR, ck = v % VPR;
            int swb = ((ck & ~7) | ((ck ^ row) & 7)) * 16;
            *(uint4*)(smc + TILEB + row * (2 * K) + swb) = Wg[v];
        }
    }
    __syncthreads();

    int warp_m = wid & 1, warp_n = wid >> 1;
    int l7 = lane & 7;

    int rowA = warp_m * 64 + l7 + ((lane >> 3) & 1) * 8;
    int ckoffA = (lane >> 4) & 1;
    int rowB = warp_n * 32 + l7 + ((lane >> 4) & 1) * 8;
    int ckoffB = (lane >> 3) & 1;

    uint32_t aAbase = sA + rowA * (2 * K);
    uint32_t aBbase = sB + rowB * (2 * K);

    float acc[4][4][4];
#pragma unroll
    for (int mi = 0; mi < 4; mi++)
#pragma unroll
        for (int ni = 0; ni < 4; ni++)
#pragma unroll
            for (int e = 0; e < 4; e++) acc[mi][ni][e] = 0.f;

#pragma unroll
    for (int ks = 0; ks < NKS; ks++) {
        int xA = ks * 2 + ckoffA;
        int xB = ks * 2 + ckoffB;
        uint32_t swbA = (uint32_t)(((xA & ~7) | ((xA ^ l7) & 7)) * 16);
        uint32_t swbB = (uint32_t)(((xB & ~7) | ((xB ^ l7) & 7)) * 16);

        uint32_t afr[4][4];
#pragma unroll
        for (int mi = 0; mi < 4; mi++)
            ldmx4(afr[mi], aAbase + (uint32_t)(mi * 16 * 2 * K) + swbA);

        uint32_t bfr[2][4];
#pragma unroll
        for (int nb = 0; nb < 2; nb++)
            ldmx4(bfr[nb], aBbase + (uint32_t)(nb * 16 * 2 * K) + swbB);

#pragma unroll
        for (int mi = 0; mi < 4; mi++)
#pragma unroll
            for (int ni = 0; ni < 4; ni++)
                mma16816(acc[mi][ni], afr[mi],
                         bfr[ni >> 1][(ni & 1) * 2], bfr[ni >> 1][(ni & 1) * 2 + 1]);
    }

    int mrow = warp_m * 64 + (lane >> 2);
    int ncol = warp_n * 32 + (lane & 3) * 2;
    float lm[4][2];
#pragma unroll
    for (int mi = 0; mi < 4; mi++) { lm[mi][0] = -1e30f; lm[mi][1] = -1e30f; }

#pragma unroll
    for (int mi = 0; mi < 4; mi++) {
#pragma unroll
        for (int ni = 0; ni < 4; ni++) {
            int bc = ncol + ni * 8;
            float bx = bias[bc], by = bias[bc + 1];
            float2 v0 = make_float2(acc[mi][ni][0] + bx, acc[mi][ni][1] + by);
            float2 v1 = make_float2(acc[mi][ni][2] + bx, acc[mi][ni][3] + by);
            if (!EMEXP) {
                size_t r0g = (row0 + mrow + mi * 16) * (size_t)Gout + col0 + bc;
                size_t r1g = r0g + 8 * (size_t)Gout;
                *(float2*)(out + r0g) = v0;
                *(float2*)(out + r1g) = v1;
            } else {
                lm[mi][0] = fmaxf(lm[mi][0], fmaxf(v0.x, v0.y));
                lm[mi][1] = fmaxf(lm[mi][1], fmaxf(v1.x, v1.y));
            }
        }
    }

    if (EMEXP) {
#pragma unroll
        for (int mi = 0; mi < 4; mi++)
#pragma unroll
            for (int h = 0; h < 2; h++) {
                lm[mi][h] = fmaxf(lm[mi][h], __shfl_xor_sync(0xffffffffu, lm[mi][h], 1));
                lm[mi][h] = fmaxf(lm[mi][h], __shfl_xor_sync(0xffffffffu, lm[mi][h], 2));
            }
        if ((lane & 3) == 0) {
#pragma unroll
            for (int mi = 0; mi < 4; mi++)
#pragma unroll
                for (int h = 0; h < 2; h++) {
                    int r128 = warp_m * 64 + (lane >> 2) + mi * 16 + h * 8;
                    smp[r128][warp_n] = lm[mi][h];
                }
        }
        __syncthreads();
#pragma unroll
        for (int mi = 0; mi < 4; mi++) {
#pragma unroll
            for (int h = 0; h < 2; h++) {
                int r128 = warp_m * 64 + (lane >> 2) + mi * 16 + h * 8;
                float rm = fmaxf(fmaxf(smp[r128][0], smp[r128][1]),
                                 fmaxf(smp[r128][2], smp[r128][3]));
                size_t rg = row0 + r128;
#pragma unroll
                for (int ni = 0; ni < 4; ni++) {
                    int bc = ncol + ni * 8;
                    float bx = bias[bc], by = bias[bc + 1];
                    float ex = __expf(acc[mi][ni][2 * h + 0] + bx - rm);
                    float ey = __expf(acc[mi][ni][2 * h + 1] + by - rm);
                    *(float2*)(&g_eem[rg * Vc + bc]) = make_float2(ex, ey);
                }
                if (warp_n == 0 && (lane & 3) == 0) g_emmax[rg] = rm;
            }
        }
    }
}

// ---------------- LSTM recurrence: warp-paired halves, 1 barrier/step ----------
// Thread (warp w, lane l): unit u = w*16 + (l&15), half hf = l>>4.
// hf=0 computes gates i (row u) and g (row u+128) for all Mb batches;
// hf=1 computes f (row 64+u) and o (row 192+u). Cross-half exchange via shfl.xor(16).
// h double-buffered -> single __syncthreads per step.
__global__ __launch_bounds__(128, 2) void k_lstm(const float* __restrict__ pre_f,
                                                 const float* __restrict__ pre_b,
                                                 const float* __restrict__ whh_f,
                                                 const float* __restrict__ whh_b,
                                                 __nv_bfloat16* __restrict__ hs) {
    int grp = blockIdx.x;
    int dir = blockIdx.y;
    const float* pre = dir ? pre_b : pre_f;
    const float* whh = dir ? whh_b : whh_f;
    int tt = threadIdx.x;
    int l = tt & 31;
    int u = (tt >> 5) * 16 + (l & 15);
    int hf = l >> 4;
    int rA = hf * 64 + u;      // i-row (hf=0) or f-row (hf=1)
    int rB = rA + 128;         // g-row (hf=0) or o-row (hf=1)
    int b0 = grp * Mb;
    int mh = hf * 2;           // cell-update batches mh, mh+1

    // actB activation constants: hf=0 -> tanh(x); hf=1 -> sigmoid = 0.5*tanh(0.5x)+0.5
    float pB = hf ? 0.5f : 1.0f;
    float sB = hf ? 0.5f : 1.0f;
    float oB = hf ? 0.5f : 0.0f;

    unsigned long long wpA[32], wpB[32];
    {
        const float4* wa = (const float4*)(whh + (size_t)rA * 64);
        const float4* wb = (const float4*)(whh + (size_t)rB * 64);
#pragma unroll
        for (int i = 0; i < 16; i++) {
            float4 va = wa[i], vb = wb[i];
            wpA[2 * i]     = pk2(va.x, va.y);
            wpA[2 * i + 1] = pk2(va.z, va.w);
            wpB[2 * i]     = pk2(vb.x, vb.y);
            wpB[2 * i + 1] = pk2(vb.z, vb.w);
        }
    }

    __shared__ __align__(16) float h_sh[2][Mb][64];

    float c[2] = {0.f, 0.f};
    if (tt < 64) ((float4*)h_sh[0])[tt] = make_float4(0.f, 0.f, 0.f, 0.f);
    __syncthreads();

    int t0 = dir ? (Tc - 1) : 0;
    float pnA[Mb], pnB[Mb];
#pragma unroll
    for (int m = 0; m < Mb; m++) {
        size_t base = ((size_t)(b0 + m) * Tc + t0) * Gc;
        pnA[m] = __ldcs(pre + base + rA);
        pnB[m] = __ldcs(pre + base + rB);
    }

    int cur = 0;
    for (int s = 0; s < Tc; s++) {
        int t = dir ? (Tc - 1 - s) : s;
        float pcA[Mb], pcB[Mb];
#pragma unroll
        for (int m = 0; m < Mb; m++) { pcA[m] = pnA[m]; pcB[m] = pnB[m]; }
        if (s + 1 < Tc) {
            int tn = dir ? (Tc - 2 - s) : (s + 1);
#pragma unroll
            for (int m = 0; m < Mb; m++) {
                size_t base = ((size_t)(b0 + m) * Tc + tn) * Gc;
                pnA[m] = __ldcs(pre + base + rA);
                pnB[m] = __ldcs(pre + base + rB);
            }
        }

        float avA[Mb], avB[Mb];
#pragma unroll
        for (int m = 0; m < Mb; m++) {
            unsigned long long a0 = 0ull, a1 = 0ull, b0a = 0ull, b1a = 0ull;
            const ulonglong2* hp = (const ulonglong2*)h_sh[cur][m];
#pragma unroll
            for (int i = 0; i < 16; i++) {
                ulonglong2 hv = hp[i];
                a0  = ffma2(wpA[2 * i],     hv.x, a0);
                a1  = ffma2(wpA[2 * i + 1], hv.y, a1);
                b0a = ffma2(wpB[2 * i],     hv.x, b0a);
                b1a = ffma2(wpB[2 * i + 1], hv.y, b1a);
            }
            float2 pa0 = unpk(a0), pa1 = unpk(a1);
            float2 pb0 = unpk(b0a), pb1 = unpk(b1a);
            avA[m] = pcA[m] + ((pa0.x + pa0.y) + (pa1.x + pa1.y));
            avB[m] = pcB[m] + ((pb0.x + pb0.y) + (pb1.x + pb1.y));
        }

        // branchless activations: actA always sigmoid; actB tanh (hf=0) / sigmoid (hf=1)
        float actA[Mb], actB[Mb];
#pragma unroll
        for (int m = 0; m < Mb; m++) {
            actA[m] = fmaf(0.5f, tanh_hw(0.5f * avA[m]), 0.5f);
            actB[m] = fmaf(sB, tanh_hw(pB * avB[m]), oB);
        }

        // cross-half exchange (partner = lane l^16, same unit u)
        float sA0 = hf ? actA[0] : actA[2];
        float sA1 = hf ? actA[1] : actA[3];
        float sB0 = hf ? actB[0] : actB[2];
        float sB1 = hf ? actB[1] : actB[3];
        float rcA0 = __shfl_xor_sync(0xffffffffu, sA0, 16);
        float rcA1 = __shfl_xor_sync(0xffffffffu, sA1, 16);
        float rcB0 = __shfl_xor_sync(0xffffffffu, sB0, 16);
        float rcB1 = __shfl_xor_sync(0xffffffffu, sB1, 16);

        // own gate values for this thread's cell-update batches (static indexing)
        float ownA0 = hf ? actA[2] : actA[0];
        float ownA1 = hf ? actA[3] : actA[1];
        float ownB0 = hf ? actB[2] : actB[0];
        float ownB1 = hf ? actB[3] : actB[1];

        int nxt = cur ^ 1;
        {
            // mm = 0
            float i_ = hf ? rcA0 : ownA0;
            float f_ = hf ? ownA0 : rcA0;
            float gg = hf ? rcB0 : ownB0;
            float o_ = hf ? ownB0 : rcB0;
            c[0] = f_ * c[0] + i_ * gg;
            float h = o_ * tanh_hw(c[0]);
            h_sh[nxt][mh][u] = h;
            hs[((size_t)(b0 + mh) * Tc + t) * 128 + dir * 64 + u] = __float2bfloat16(h);
        }
        {
            // mm = 1
            float i_ = hf ? rcA1 : ownA1;
            float f_ = hf ? ownA1 : rcA1;
            float gg = hf ? rcB1 : ownB1;
            float o_ = hf ? ownB1 : rcB1;
            c[1] = f_ * c[1] + i_ * gg;
            float h = o_ * tanh_hw(c[1]);
            h_sh[nxt][mh + 1][u] = h;
            hs[((size_t)(b0 + mh + 1) * Tc + t) * 128 + dir * 64 + u] = __float2bfloat16(h);
        }
        __syncthreads();
        cur = nxt;
    }
}

// ---------------- fused CRF prep: sequence lengths + exp(trans)^T ----------------
__global__ void k_prep(const int* __restrict__ x, const float* __restrict__ trans) {
    int blk = blockIdx.x;
    if (blk < Bc) {
        __shared__ int red[256];
        int tid = threadIdx.x;
        red[tid] = (x[blk * Tc + tid] != 0) ? 1 : 0;
        __syncthreads();
        for (int s = 128; s; s >>= 1) {
            if (tid < s) red[tid] += red[tid + s];
            __syncthreads();
        }
        if (tid == 0) g_len[blk] = red[0];
    } else {
        int idx = (blk - Bc) * 256 + threadIdx.x;
        if (idx < Vc * Vc) {
            int j = idx >> 7, i = idx & 127;
            g_MexpT[idx] = __expf(trans[i * Vc + j]);
        }
    }
}

// ---------------- CRF forward (M in registers, 256 threads) ----------------
__device__ __forceinline__ float bmax256(float v, float* red) {
#pragma unroll
    for (int o = 16; o; o >>= 1) v = fmaxf(v, __shfl_xor_sync(0xffffffffu, v, o));
    __syncthreads();
    if ((threadIdx.x & 31) == 0) red[threadIdx.x >> 5] = v;
    __syncthreads();
    float m = fmaxf(fmaxf(fmaxf(red[0], red[1]), fmaxf(red[2], red[3])),
                    fmaxf(fmaxf(red[4], red[5]), fmaxf(red[6], red[7])));
    return m;
}
__device__ __forceinline__ float bsum256(float v, float* red) {
#pragma unroll
    for (int o = 16; o; o >>= 1) v += __shfl_xor_sync(0xffffffffu, v, o);
    __syncthreads();
    if ((threadIdx.x & 31) == 0) red[threadIdx.x >> 5] = v;
    __syncthreads();
    return ((red[0] + red[1]) + (red[2] + red[3])) +
           ((red[4] + red[5]) + (red[6] + red[7]));
}

__global__ __launch_bounds__(256) void k_crf(const float* __restrict__ startv,
                                             const float* __restrict__ endv) {
    __shared__ __align__(16) float a_sh[2][Vc];
    __shared__ float red[8];
    int b = blockIdx.x;
    int tt = threadIdx.x;
    int w = tt >> 5, l = tt & 31;
    int j = w * 16 + (l & 15);
    int half = l >> 4;

    unsigned long long Mreg[32];
    {
        const float4* msrc = (const float4*)(g_MexpT + (size_t)j * Vc + half * 64);
#pragma unroll
        for (int i = 0; i < 16; i++) {
            float4 v = msrc[i];
            Mreg[2 * i]     = pk2(v.x, v.y);
            Mreg[2 * i + 1] = pk2(v.z, v.w);
        }
    }

    int len = g_len[b];
    // em[b,0,j] = emmax[b,0] + log(eem[b,0,j])
    float al0 = startv[j] + g_emmax[b * Tc] + __logf(g_eem[(size_t)b * Tc * Vc + j]);
    float m = bmax256(al0, red);
    if (half == 0) a_sh[0][j] = __expf(al0 - m);
    float off = m;
    __syncthreads();

    const float LOG128 = 4.852030263919617f;
    int cur = 0;

    for (int t = 1; t < len; t++) {
        float ee  = g_eem[((size_t)b * Tc + t) * Vc + j];
        float emx = g_emmax[b * Tc + t];
        unsigned long long s0 = 0ull, s1 = 0ull;
        const ulonglong2* ap = (const ulonglong2*)(a_sh[cur] + half * 64);
#pragma unroll
        for (int i = 0; i < 16; i += 2) {
            ulonglong2 a0v = ap[i], a1v = ap[i + 1];
            s0 = ffma2(a0v.x, Mreg[2 * i],     s0);
            s1 = ffma2(a0v.y, Mreg[2 * i + 1], s1);
            s0 = ffma2(a1v.x, Mreg[2 * i + 2], s0);
            s1 = ffma2(a1v.y, Mreg[2 * i + 3], s1);
        }
        float2 p0 = unpk(s0), p1 = unpk(s1);
        float part = (p0.x + p0.y) + (p1.x + p1.y);
        part += __shfl_xor_sync(0xffffffffu, part, 16);
        float v = part * ee;
        if ((t & 15) == 0) {
            float vmax = bmax256(v, red);
            if (half == 0) a_sh[cur ^ 1][j] = v * (1.f / vmax);
            off += emx + __logf(vmax);
        } else {
            if (half == 0) a_sh[cur ^ 1][j] = v * 0.0078125f;
            off += emx + LOG128;
        }
        cur ^= 1;
        __syncthreads();
    }

    float term = (half == 0) ? a_sh[cur][j] * __expf(endv[j]) : 0.f;
    float ssum = bsum256(term, red);
    if (tt == 0) g_part[b] = off + __logf(ssum);
}

// ---------------- gold-path score (em reconstructed from eem/emmax) ----------------
__global__ void k_score(const int* __restrict__ tags, const float* __restrict__ trans,
                        const float* __restrict__ startv, const float* __restrict__ endv) {
    int gw = (blockIdx.x * blockDim.x + threadIdx.x) >> 5;
    int lane = threadIdx.x & 31;
    if (gw >= Bc) return;
    int b = gw;
    int len = g_len[b];
    float s = 0.f;
    for (int t = 1 + lane; t < len; t += 32) {
        int tp  = tags[b * Tc + t - 1];
        int tcu = tags[b * Tc + t];
        float em = g_emmax[b * Tc + t] + __logf(g_eem[((size_t)b * Tc + t) * Vc + tcu]);
        s += trans[tp * Vc + tcu] + em;
    }
#pragma unroll
    for (int o = 16; o; o >>= 1) s += __shfl_xor_sync(0xffffffffu, s, o);
    if (lane == 0) {
        int t0 = tags[b * Tc];
        int tl = tags[b * Tc + len - 1];
        float em0 = g_emmax[b * Tc] + __logf(g_eem[(size_t)b * Tc * Vc + t0]);
        s += startv[t0] + em0 + endv[tl];
        g_scorev[b] = s;
    }
}

// ---------------- final reduction ----------------
__global__ void k_final(float* __restrict__ out) {
    __shared__ float red[512];
    int t = threadIdx.x;
    red[t] = g_scorev[t] - g_part[t];
    __syncthreads();
    for (int s = 256; s; s >>= 1) {
        if (t < s) red[t] += red[t + s];
        __syncthreads();
    }
    if (t == 0) out[0] = -red[0] * (1.f / Bc);
}

// ---------------- host launcher ----------------
extern "C" void kernel_launch(void* const* d_in, const int* in_sizes, int n_in,
                              void* d_out, int out_size) {
    const int*   x        = (const int*)d_in[0];
    const int*   tags     = (const int*)d_in[1];
    const float* emb      = (const float*)d_in[2];
    const float* w_ih_l0  = (const float*)d_in[3];
    const float* w_hh_l0  = (const float*)d_in[4];
    const float* b_ih_l0  = (const float*)d_in[5];
    const float* b_hh_l0  = (const float*)d_in[6];
    const float* w_ih_l0r = (const float*)d_in[7];
    const float* w_hh_l0r = (const float*)d_in[8];
    const float* b_ih_l0r = (const float*)d_in[9];
    const float* b_hh_l0r = (const float*)d_in[10];
    const float* w_ih_l1  = (const float*)d_in[11];
    const float* w_hh_l1  = (const float*)d_in[12];
    const float* b_ih_l1  = (const float*)d_in[13];
    const float* b_hh_l1  = (const float*)d_in[14];
    const float* w_ih_l1r = (const float*)d_in[15];
    const float* w_hh_l1r = (const float*)d_in[16];
    const float* b_ih_l1r = (const float*)d_in[17];
    const float* b_hh_l1r = (const float*)d_in[18];
    const float* lin_w    = (const float*)d_in[19];
    const float* lin_b    = (const float*)d_in[20];
    const float* crf_start = (const float*)d_in[21];
    const float* crf_end   = (const float*)d_in[22];
    const float* crf_trans = (const float*)d_in[23];
    float* out = (float*)d_out;

    __nv_bfloat16 *px0, *phs0, *phs1, *pw0f, *pw0b, *pw1f, *pw1b, *plw;
    float *ppf, *ppb, *pdm;
    cudaGetSymbolAddress((void**)&px0,  g_x0b);
    cudaGetSymbolAddress((void**)&ppf,  g_pre_f);
    cudaGetSymbolAddress((void**)&ppb,  g_pre_b);
    cudaGetSymbolAddress((void**)&phs0, g_hs0b);
    cudaGetSymbolAddress((void**)&phs1, g_hs1b);
    cudaGetSymbolAddress((void**)&pdm,  g_dummy);
    cudaGetSymbolAddress((void**)&pw0f, g_wih0f);
    cudaGetSymbolAddress((void**)&pw0b, g_wih0b);
    cudaGetSymbolAddress((void**)&pw1f, g_wih1f);
    cudaGetSymbolAddress((void**)&pw1b, g_wih1b);
    cudaGetSymbolAddress((void**)&plw,  g_linwb);

    const int SM64  = 2 * 128 * 64 * 2;    // 32KB
    const int SM128 = 2 * 128 * 128 * 2;   // 64KB
    cudaFuncSetAttribute(k_mma<64, false>,  cudaFuncAttributeMaxDynamicSharedMemorySize, SM64);
    cudaFuncSetAttribute(k_mma<128, false>, cudaFuncAttributeMaxDynamicSharedMemorySize, SM128);
    cudaFuncSetAttribute(k_mma<128, true>,  cudaFuncAttributeMaxDynamicSharedMemorySize, SM128);

    const int NROW = Bc * Tc;  // 131072
    const int NT = NROW / 128; // 1024 tiles

    // fused weight conversions + embedding + CRF prep (no inter-deps)
    k_cvt5<<<(114688 + 255) / 256, 256>>>(w_ih_l0, w_ih_l0r, w_ih_l1, w_ih_l1r, lin_w);
    k_embed<<<(Bc * Tc * Ec / 8 + 255) / 256, 256>>>(x, emb);
    k_prep<<<Bc + 64, 256>>>(x, crf_trans);

    // layer 0 pre-activations (K=64, Gout=256): fwd+bwd fused via gridDim.z
    k_mma<64, false><<<dim3(NT, 2, 2), 256, SM64>>>(
        px0, pw0f, pw0b, b_ih_l0, b_ih_l0r, b_hh_l0, b_hh_l0r, ppf, ppb, Gc);
    k_lstm<<<dim3(Bc / Mb, 2), 128>>>(ppf, ppb, w_hh_l0, w_hh_l0r, phs0);

    // layer 1 pre-activations (K=128, Gout=256): fwd+bwd fused
    k_mma<128, false><<<dim3(NT, 2, 2), 256, SM128>>>(
        phs0, pw1f, pw1b, b_ih_l1, b_ih_l1r, b_hh_l1, b_hh_l1r, ppf, ppb, Gc);
    k_lstm<<<dim3(Bc / Mb, 2), 128>>>(ppf, ppb, w_hh_l1, w_hh_l1r, phs1);

    // emissions (K=128, Gout=128): writes only eem/emmax
    k_mma<128, true><<<dim3(NT, 1, 1), 256, SM128>>>(
        phs1, plw, plw, lin_b, lin_b, nullptr, nullptr, pdm, pdm, Vc);

    // CRF (M in registers)
    k_crf<<<Bc, 256>>>(crf_start, crf_end);
    k_score<<<Bc / 8, 256>>>(tags, crf_trans, crf_start, crf_end);
    k_final<<<1, 512>>>(out);
}

// round 15
// speedup vs baseline: 1.1486x; 1.1486x over previous
#include <cuda_runtime.h>
#include <cuda_bf16.h>
#include <cstdint>

#define Bc 512
#define Tc 256
#define Vc 128
#define Ec 64
#define Hc 64
#define Gc 256  // 4*H
#define Mb 4    // batches per LSTM CTA

// ---------------- scratch (static device globals; no allocation) ----------------
__device__ __nv_bfloat16 g_x0b [(size_t)Bc*Tc*Ec];
__device__ float g_pre_f[(size_t)Bc*Tc*Gc];
__device__ float g_pre_b[(size_t)Bc*Tc*Gc];
__device__ __nv_bfloat16 g_hs0b[(size_t)Bc*Tc*2*Hc];
__device__ __nv_bfloat16 g_hs1b[(size_t)Bc*Tc*2*Hc];
__device__ float g_eem  [(size_t)Bc*Tc*Vc];
__device__ float g_emmax[Bc*Tc];
__device__ float g_MexpT[Vc*Vc];
__device__ int   g_len  [Bc];
__device__ float g_scorev[Bc];
__device__ float g_part [Bc];
__device__ float g_dummy[(size_t)Bc*Tc*Vc];   // unused out target for emissions
// bf16 weights
__device__ __nv_bfloat16 g_wih0f[Gc*Ec];
__device__ __nv_bfloat16 g_wih0b[Gc*Ec];
__device__ __nv_bfloat16 g_wih1f[Gc*2*Hc];
__device__ __nv_bfloat16 g_wih1b[Gc*2*Hc];
__device__ __nv_bfloat16 g_linwb[Vc*2*Hc];

// ---------------- helpers ----------------
__device__ __forceinline__ uint32_t smem_u32(const void* p) {
    uint32_t a;
    asm("{ .reg .u64 t; cvta.to.shared.u64 t, %1; cvt.u32.u64 %0, t; }" : "=r"(a) : "l"(p));
    return a;
}
__device__ __forceinline__ unsigned long long pk2(float x, float y) {
    unsigned long long r;
    asm("mov.b64 %0, {%1, %2};" : "=l"(r) : "f"(x), "f"(y));
    return r;
}
__device__ __forceinline__ unsigned long long ffma2(unsigned long long a,
                                                    unsigned long long b,
                                                    unsigned long long c) {
    unsigned long long d;
    asm("fma.rn.f32x2 %0, %1, %2, %3;" : "=l"(d) : "l"(a), "l"(b), "l"(c));
    return d;
}
__device__ __forceinline__ float2 unpk(unsigned long long v) {
    float2 r;
    asm("mov.b64 {%0, %1}, %2;" : "=f"(r.x), "=f"(r.y) : "l"(v));
    return r;
}
__device__ __forceinline__ float tanh_hw(float x) {
    float r;
    asm("tanh.approx.f32 %0, %1;" : "=f"(r) : "f"(x));
    return r;
}
__device__ __forceinline__ float sigmoid_hw(float x) {
    return fmaf(0.5f, tanh_hw(0.5f * x), 0.5f);
}
__device__ __forceinline__ void ldmx4(uint32_t* r, uint32_t addr) {
    asm volatile("ldmatrix.sync.aligned.m8n8.x4.shared.b16 {%0,%1,%2,%3}, [%4];"
                 : "=r"(r[0]), "=r"(r[1]), "=r"(r[2]), "=r"(r[3]) : "r"(addr));
}
__device__ __forceinline__ void mma16816(float* c, const uint32_t* a, uint32_t b0, uint32_t b1) {
    asm volatile(
        "mma.sync.aligned.m16n8k16.row.col.f32.bf16.bf16.f32 "
        "{%0,%1,%2,%3}, {%4,%5,%6,%7}, {%8,%9}, {%0,%1,%2,%3};"
        : "+f"(c[0]), "+f"(c[1]), "+f"(c[2]), "+f"(c[3])
        : "r"(a[0]), "r"(a[1]), "r"(a[2]), "r"(a[3]), "r"(b0), "r"(b1));
}

// ---------------- fused weight fp32 -> bf16 (all 5 weights) ----------------
__global__ void k_cvt5(const float* __restrict__ s0, const float* __restrict__ s1,
                       const float* __restrict__ s2, const float* __restrict__ s3,
                       const float* __restrict__ s4) {
    int i = blockIdx.x * blockDim.x + threadIdx.x;
    if (i < 16384)            g_wih0f[i] = __float2bfloat16(s0[i]);
    else if (i < 32768)       g_wih0b[i - 16384] = __float2bfloat16(s1[i - 16384]);
    else if (i < 65536)       g_wih1f[i - 32768] = __float2bfloat16(s2[i - 32768]);
    else if (i < 98304)       g_wih1b[i - 65536] = __float2bfloat16(s3[i - 65536]);
    else if (i < 114688)      g_linwb[i - 98304] = __float2bfloat16(s4[i - 98304]);
}

// ---------------- embedding gather (bf16 out, 8 elems/thread) ----------------
__global__ void k_embed(const int* __restrict__ x, const float* __restrict__ emb) {
    size_t i = (size_t)blockIdx.x * blockDim.x + threadIdx.x;
    if (i >= (size_t)Bc * Tc * Ec / 8) return;
    size_t n = i >> 3;
    int   e = (int)(i & 7) * 8;
    const float4* src = (const float4*)(emb + (size_t)x[n] * Ec + e);
    float4 v0 = src[0], v1 = src[1];
    __nv_bfloat16 o[8];
    o[0] = __float2bfloat16(v0.x); o[1] = __float2bfloat16(v0.y);
    o[2] = __float2bfloat16(v0.z); o[3] = __float2bfloat16(v0.w);
    o[4] = __float2bfloat16(v1.x); o[5] = __float2bfloat16(v1.y);
    o[6] = __float2bfloat16(v1.z); o[7] = __float2bfloat16(v1.w);
    *(uint4*)(g_x0b + i * 8) = *(uint4*)o;
}

// ---------------- HMMA GEMM: out[r, n] = sum_k A[r,k]*W[n,k] + bias ----------------
// blockIdx.z selects the (W, bias, out) set. EMEXP: write only eem/emmax (no out store).
template <int K, bool EMEXP>
__global__ __launch_bounds__(256) void k_mma(const __nv_bfloat16* __restrict__ A,
                                             const __nv_bfloat16* __restrict__ Wf,
                                             const __nv_bfloat16* __restrict__ Wb,
                                             const float* __restrict__ b1f,
                                             const float* __restrict__ b1b,
                                             const float* __restrict__ b2f,
                                             const float* __restrict__ b2b,
                                             float* __restrict__ outf,
                                             float* __restrict__ outb, int Gout) {
    constexpr int VPR   = K / 8;
    constexpr int TILEB = 128 * K * 2;
    constexpr int NKS   = K / 16;

    extern __shared__ char sm[];
    __shared__ float bias[128];
    __shared__ float smp[128][4];

    const __nv_bfloat16* W = blockIdx.z ? Wb : Wf;
    const float* b1 = blockIdx.z ? b1b : b1f;
    const float* b2 = blockIdx.z ? b2b : b2f;
    float* out = blockIdx.z ? outb : outf;

    uint32_t sA = smem_u32(sm);
    uint32_t sB = sA + TILEB;

    int tid = threadIdx.x, wid = tid >> 5, lane = tid & 31;
    size_t row0 = (size_t)blockIdx.x * 128;
    int    col0 = blockIdx.y * 128;

    if (tid < 128) bias[tid] = b1[col0 + tid] + (b2 ? b2[col0 + tid] : 0.f);

    {
        const uint4* Ag = (const uint4*)(A + row0 * K);
        const uint4* Wg = (const uint4*)(W + (size_t)col0 * K);
        char* smc = sm;
#pragma unroll 4
        for (int v = tid; v < 128 * VPR; v += 256) {
            int row = v / VPR, ck = v % VPR;
            int swb = ((ck & ~7) | ((ck ^ row) & 7)) * 16;
            *(uint4*)(smc + row * (2 * K) + swb) = Ag[v];
        }
#pragma unroll 4
        for (int v = tid; v < 128 * VPR; v += 256) {
            int row = v / VPR, ck = v % VPR;
            int swb = ((ck & ~7) | ((ck ^ row) & 7)) * 16;
            *(uint4*)(smc + TILEB + row * (2 * K) + swb) = Wg[v];
        }
    }
    __syncthreads();

    int warp_m = wid & 1, warp_n = wid >> 1;
    int l7 = lane & 7;

    int rowA = warp_m * 64 + l7 + ((lane >> 3) & 1) * 8;
    int ckoffA = (lane >> 4) & 1;
    int rowB = warp_n * 32 + l7 + ((lane >> 4) & 1) * 8;
    int ckoffB = (lane >> 3) & 1;

    uint32_t aAbase = sA + rowA * (2 * K);
    uint32_t aBbase = sB + rowB * (2 * K);

    float acc[4][4][4];
#pragma unroll
    for (int mi = 0; mi < 4; mi++)
#pragma unroll
        for (int ni = 0; ni < 4; ni++)
#pragma unroll
            for (int e = 0; e < 4; e++) acc[mi][ni][e] = 0.f;

#pragma unroll
    for (int ks = 0; ks < NKS; ks++) {
        int xA = ks * 2 + ckoffA;
        int xB = ks * 2 + ckoffB;
        uint32_t swbA = (uint32_t)(((xA & ~7) | ((xA ^ l7) & 7)) * 16);
        uint32_t swbB = (uint32_t)(((xB & ~7) | ((xB ^ l7) & 7)) * 16);

        uint32_t afr[4][4];
#pragma unroll
        for (int mi = 0; mi < 4; mi++)
            ldmx4(afr[mi], aAbase + (uint32_t)(mi * 16 * 2 * K) + swbA);

        uint32_t bfr[2][4];
#pragma unroll
        for (int nb = 0; nb < 2; nb++)
            ldmx4(bfr[nb], aBbase + (uint32_t)(nb * 16 * 2 * K) + swbB);

#pragma unroll
        for (int mi = 0; mi < 4; mi++)
#pragma unroll
            for (int ni = 0; ni < 4; ni++)
                mma16816(acc[mi][ni], afr[mi],
                         bfr[ni >> 1][(ni & 1) * 2], bfr[ni >> 1][(ni & 1) * 2 + 1]);
    }

    int mrow = warp_m * 64 + (lane >> 2);
    int ncol = warp_n * 32 + (lane & 3) * 2;
    float lm[4][2];
#pragma unroll
    for (int mi = 0; mi < 4; mi++) { lm[mi][0] = -1e30f; lm[mi][1] = -1e30f; }

#pragma unroll
    for (int mi = 0; mi < 4; mi++) {
#pragma unroll
        for (int ni = 0; ni < 4; ni++) {
            int bc = ncol + ni * 8;
            float bx = bias[bc], by = bias[bc + 1];
            float2 v0 = make_float2(acc[mi][ni][0] + bx, acc[mi][ni][1] + by);
            float2 v1 = make_float2(acc[mi][ni][2] + bx, acc[mi][ni][3] + by);
            if (!EMEXP) {
                size_t r0g = (row0 + mrow + mi * 16) * (size_t)Gout + col0 + bc;
                size_t r1g = r0g + 8 * (size_t)Gout;
                *(float2*)(out + r0g) = v0;
                *(float2*)(out + r1g) = v1;
            } else {
                lm[mi][0] = fmaxf(lm[mi][0], fmaxf(v0.x, v0.y));
                lm[mi][1] = fmaxf(lm[mi][1], fmaxf(v1.x, v1.y));
            }
        }
    }

    if (EMEXP) {
#pragma unroll
        for (int mi = 0; mi < 4; mi++)
#pragma unroll
            for (int h = 0; h < 2; h++) {
                lm[mi][h] = fmaxf(lm[mi][h], __shfl_xor_sync(0xffffffffu, lm[mi][h], 1));
                lm[mi][h] = fmaxf(lm[mi][h], __shfl_xor_sync(0xffffffffu, lm[mi][h], 2));
            }
        if ((lane & 3) == 0) {
#pragma unroll
            for (int mi = 0; mi < 4; mi++)
#pragma unroll
                for (int h = 0; h < 2; h++) {
                    int r128 = warp_m * 64 + (lane >> 2) + mi * 16 + h * 8;
                    smp[r128][warp_n] = lm[mi][h];
                }
        }
        __syncthreads();
#pragma unroll
        for (int mi = 0; mi < 4; mi++) {
#pragma unroll
            for (int h = 0; h < 2; h++) {
                int r128 = warp_m * 64 + (lane >> 2) + mi * 16 + h * 8;
                float rm = fmaxf(fmaxf(smp[r128][0], smp[r128][1]),
                                 fmaxf(smp[r128][2], smp[r128][3]));
                size_t rg = row0 + r128;
#pragma unroll
                for (int ni = 0; ni < 4; ni++) {
                    int bc = ncol + ni * 8;
                    float bx = bias[bc], by = bias[bc + 1];
                    float ex = __expf(acc[mi][ni][2 * h + 0] + bx - rm);
                    float ey = __expf(acc[mi][ni][2 * h + 1] + by - rm);
                    *(float2*)(&g_eem[rg * Vc + bc]) = make_float2(ex, ey);
                }
                if (warp_n == 0 && (lane & 3) == 0) g_emmax[rg] = rm;
            }
        }
    }
}

// ---------------- LSTM recurrence: 128 threads, 2 gate rows per thread, Mb=4 ----
// (R13 version: cross-half gate exchange via smem, 2 barriers/step)
__global__ __launch_bounds__(128, 2) void k_lstm(const float* __restrict__ pre_f,
                                                 const float* __restrict__ pre_b,
                                                 const float* __restrict__ whh_f,
                                                 const float* __restrict__ whh_b,
                                                 __nv_bfloat16* __restrict__ hs) {
    int grp = blockIdx.x;
    int dir = blockIdx.y;
    const float* pre = dir ? pre_b : pre_f;
    const float* whh = dir ? whh_b : whh_f;
    int tt = threadIdx.x;
    int j2 = tt & 63, hf = tt >> 6;
    int rA = tt;           // rows 0-63: gate i | 64-127: gate f
    int rB = rA + 128;     // rows 128-191: gate g | 192-255: gate o
    int b0 = grp * Mb;
    int mh = hf * 2;       // this thread's 2 cell-update batches

    unsigned long long wpA[32], wpB[32];
    {
        const float4* wa = (const float4*)(whh + (size_t)rA * 64);
        const float4* wb = (const float4*)(whh + (size_t)rB * 64);
#pragma unroll
        for (int i = 0; i < 16; i++) {
            float4 va = wa[i], vb = wb[i];
            wpA[2 * i]     = pk2(va.x, va.y);
            wpA[2 * i + 1] = pk2(va.z, va.w);
            wpB[2 * i]     = pk2(vb.x, vb.y);
            wpB[2 * i + 1] = pk2(vb.z, vb.w);
        }
    }

    __shared__ __align__(16) float h_sh[Mb][64];
    // cross-half exchange only: [0]=i(m=2,3), [1]=f(m=0,1), [2]=g(m=2,3), [3]=o(m=0,1)
    __shared__ float acts[4][2][64];

    float c[2] = {0.f, 0.f};
    if (tt < Mb * 16) ((float4*)h_sh)[tt] = make_float4(0.f, 0.f, 0.f, 0.f);
    __syncthreads();

    int t0 = dir ? (Tc - 1) : 0;
    float pnA[Mb], pnB[Mb];
#pragma unroll
    for (int m = 0; m < Mb; m++) {
        size_t base = ((size_t)(b0 + m) * Tc + t0) * Gc;
        pnA[m] = __ldcs(pre + base + rA);
        pnB[m] = __ldcs(pre + base + rB);
    }

    for (int s = 0; s < Tc; s++) {
        int t = dir ? (Tc - 1 - s) : s;
        float pcA[Mb], pcB[Mb];
#pragma unroll
        for (int m = 0; m < Mb; m++) { pcA[m] = pnA[m]; pcB[m] = pnB[m]; }
        if (s + 1 < Tc) {
            int tn = dir ? (Tc - 2 - s) : (s + 1);
#pragma unroll
            for (int m = 0; m < Mb; m++) {
                size_t base = ((size_t)(b0 + m) * Tc + tn) * Gc;
                pnA[m] = __ldcs(pre + base + rA);
                pnB[m] = __ldcs(pre + base + rB);
            }
        }

        float avA[Mb], avB[Mb];
#pragma unroll
        for (int m = 0; m < Mb; m++) {
            unsigned long long a0 = 0ull, a1 = 0ull, b0a = 0ull, b1a = 0ull;
            const ulonglong2* hp = (const ulonglong2*)h_sh[m];
#pragma unroll
            for (int i = 0; i < 16; i++) {
                ulonglong2 hv = hp[i];
                a0  = ffma2(wpA[2 * i],     hv.x, a0);
                a1  = ffma2(wpA[2 * i + 1], hv.y, a1);
                b0a = ffma2(wpB[2 * i],     hv.x, b0a);
                b1a = ffma2(wpB[2 * i + 1], hv.y, b1a);
            }
            float2 pa0 = unpk(a0), pa1 = unpk(a1);
            float2 pb0 = unpk(b0a), pb1 = unpk(b1a);
            avA[m] = pcA[m] + ((pa0.x + pa0.y) + (pa1.x + pa1.y));
            avB[m] = pcB[m] + ((pb0.x + pb0.y) + (pb1.x + pb1.y));
        }

        // activations: hf=0 -> avA=i (sig), avB=g (tanh); hf=1 -> avA=f, avB=o (sig)
        float actA[Mb], actB[Mb];
        if (hf == 0) {
#pragma unroll
            for (int m = 0; m < Mb; m++) {
                actA[m] = sigmoid_hw(avA[m]);
                actB[m] = tanh_hw(avB[m]);
            }
            // publish i,g for m in {2,3} (needed by hf=1)
            acts[0][0][j2] = actA[2]; acts[0][1][j2] = actA[3];
            acts[2][0][j2] = actB[2]; acts[2][1][j2] = actB[3];
        } else {
#pragma unroll
            for (int m = 0; m < Mb; m++) {
                actA[m] = sigmoid_hw(avA[m]);
                actB[m] = sigmoid_hw(avB[m]);
            }
            // publish f,o for m in {0,1} (needed by hf=0)
            acts[1][0][j2] = actA[0]; acts[1][1][j2] = actA[1];
            acts[3][0][j2] = actB[0]; acts[3][1][j2] = actB[1];
        }
        __syncthreads();

#pragma unroll
        for (int mm = 0; mm < 2; mm++) {
            int m = mh + mm;
            float i_, f_, gg, o_;
            if (hf == 0) {   // m in {0,1}: own i,g; read f,o
                i_ = actA[m]; gg = actB[m];
                f_ = acts[1][mm][j2]; o_ = acts[3][mm][j2];
            } else {         // m in {2,3}: own f,o; read i,g
                f_ = actA[m]; o_ = actB[m];
                i_ = acts[0][mm][j2]; gg = acts[2][mm][j2];
            }
            c[mm] = f_ * c[mm] + i_ * gg;
            float h = o_ * tanh_hw(c[mm]);
            h_sh[m][j2] = h;
            hs[((size_t)(b0 + m) * Tc + t) * 128 + dir * 64 + j2] = __float2bfloat16(h);
        }
        __syncthreads();
    }
}

// ---------------- fused CRF prep: sequence lengths + exp(trans)^T ----------------
__global__ void k_prep(const int* __restrict__ x, const float* __restrict__ trans) {
    int blk = blockIdx.x;
    if (blk < Bc) {
        __shared__ int red[256];
        int tid = threadIdx.x;
        red[tid] = (x[blk * Tc + tid] != 0) ? 1 : 0;
        __syncthreads();
        for (int s = 128; s; s >>= 1) {
            if (tid < s) red[tid] += red[tid + s];
            __syncthreads();
        }
        if (tid == 0) g_len[blk] = red[0];
    } else {
        int idx = (blk - Bc) * 256 + threadIdx.x;
        if (idx < Vc * Vc) {
            int j = idx >> 7, i = idx & 127;
            g_MexpT[idx] = __expf(trans[i * Vc + j]);
        }
    }
}

// ---------------- CRF forward (M in registers, 256 threads) ----------------
__device__ __forceinline__ float bmax256(float v, float* red) {
#pragma unroll
    for (int o = 16; o; o >>= 1) v = fmaxf(v, __shfl_xor_sync(0xffffffffu, v, o));
    __syncthreads();
    if ((threadIdx.x & 31) == 0) red[threadIdx.x >> 5] = v;
    __syncthreads();
    float m = fmaxf(fmaxf(fmaxf(red[0], red[1]), fmaxf(red[2], red[3])),
                    fmaxf(fmaxf(red[4], red[5]), fmaxf(red[6], red[7])));
    return m;
}
__device__ __forceinline__ float bsum256(float v, float* red) {
#pragma unroll
    for (int o = 16; o; o >>= 1) v += __shfl_xor_sync(0xffffffffu, v, o);
    __syncthreads();
    if ((threadIdx.x & 31) == 0) red[threadIdx.x >> 5] = v;
    __syncthreads();
    return ((red[0] + red[1]) + (red[2] + red[3])) +
           ((red[4] + red[5]) + (red[6] + red[7]));
}

__global__ __launch_bounds__(256) void k_crf(const float* __restrict__ startv,
                                             const float* __restrict__ endv) {
    __shared__ __align__(16) float a_sh[2][Vc];
    __shared__ float red[8];
    int b = blockIdx.x;
    int tt = threadIdx.x;
    int w = tt >> 5, l = tt & 31;
    int j = w * 16 + (l & 15);
    int half = l >> 4;

    unsigned long long Mreg[32];
    {
        const float4* msrc = (const float4*)(g_MexpT + (size_t)j * Vc + half * 64);
#pragma unroll
        for (int i = 0; i < 16; i++) {
            float4 v = msrc[i];
            Mreg[2 * i]     = pk2(v.x, v.y);
            Mreg[2 * i + 1] = pk2(v.z, v.w);
        }
    }

    int len = g_len[b];
    // em[b,0,j] = emmax[b,0] + log(eem[b,0,j])
    float al0 = startv[j] + g_emmax[b * Tc] + __logf(g_eem[(size_t)b * Tc * Vc + j]);
    float m = bmax256(al0, red);
    if (half == 0) a_sh[0][j] = __expf(al0 - m);
    float off = m;
    __syncthreads();

    const float LOG128 = 4.852030263919617f;
    int cur = 0;

    for (int t = 1; t < len; t++) {
        float ee  = g_eem[((size_t)b * Tc + t) * Vc + j];
        float emx = g_emmax[b * Tc + t];
        unsigned long long s0 = 0ull, s1 = 0ull;
        const ulonglong2* ap = (const ulonglong2*)(a_sh[cur] + half * 64);
#pragma unroll
        for (int i = 0; i < 16; i += 2) {
            ulonglong2 a0v = ap[i], a1v = ap[i + 1];
            s0 = ffma2(a0v.x, Mreg[2 * i],     s0);
            s1 = ffma2(a0v.y, Mreg[2 * i + 1], s1);
            s0 = ffma2(a1v.x, Mreg[2 * i + 2], s0);
            s1 = ffma2(a1v.y, Mreg[2 * i + 3], s1);
        }
        float2 p0 = unpk(s0), p1 = unpk(s1);
        float part = (p0.x + p0.y) + (p1.x + p1.y);
        part += __shfl_xor_sync(0xffffffffu, part, 16);
        float v = part * ee;
        if ((t & 15) == 0) {
            float vmax = bmax256(v, red);
            if (half == 0) a_sh[cur ^ 1][j] = v * (1.f / vmax);
            off += emx + __logf(vmax);
        } else {
            if (half == 0) a_sh[cur ^ 1][j] = v * 0.0078125f;
            off += emx + LOG128;
        }
        cur ^= 1;
        __syncthreads();
    }

    float term = (half == 0) ? a_sh[cur][j] * __expf(endv[j]) : 0.f;
    float ssum = bsum256(term, red);
    if (tt == 0) g_part[b] = off + __logf(ssum);
}

// ---------------- gold-path score (em reconstructed from eem/emmax) ----------------
__global__ void k_score(const int* __restrict__ tags, const float* __restrict__ trans,
                        const float* __restrict__ startv, const float* __restrict__ endv) {
    int gw = (blockIdx.x * blockDim.x + threadIdx.x) >> 5;
    int lane = threadIdx.x & 31;
    if (gw >= Bc) return;
    int b = gw;
    int len = g_len[b];
    float s = 0.f;
    for (int t = 1 + lane; t < len; t += 32) {
        int tp  = tags[b * Tc + t - 1];
        int tcu = tags[b * Tc + t];
        float em = g_emmax[b * Tc + t] + __logf(g_eem[((size_t)b * Tc + t) * Vc + tcu]);
        s += trans[tp * Vc + tcu] + em;
    }
#pragma unroll
    for (int o = 16; o; o >>= 1) s += __shfl_xor_sync(0xffffffffu, s, o);
    if (lane == 0) {
        int t0 = tags[b * Tc];
        int tl = tags[b * Tc + len - 1];
        float em0 = g_emmax[b * Tc] + __logf(g_eem[(size_t)b * Tc * Vc + t0]);
        s += startv[t0] + em0 + endv[tl];
        g_scorev[b] = s;
    }
}

// ---------------- final reduction ----------------
__global__ void k_final(float* __restrict__ out) {
    __shared__ float red[512];
    int t = threadIdx.x;
    red[t] = g_scorev[t] - g_part[t];
    __syncthreads();
    for (int s = 256; s; s >>= 1) {
        if (t < s) red[t] += red[t + s];
        __syncthreads();
    }
    if (t == 0) out[0] = -red[0] * (1.f / Bc);
}

// ---------------- host launcher ----------------
extern "C" void kernel_launch(void* const* d_in, const int* in_sizes, int n_in,
                              void* d_out, int out_size) {
    const int*   x        = (const int*)d_in[0];
    const int*   tags     = (const int*)d_in[1];
    const float* emb      = (const float*)d_in[2];
    const float* w_ih_l0  = (const float*)d_in[3];
    const float* w_hh_l0  = (const float*)d_in[4];
    const float* b_ih_l0  = (const float*)d_in[5];
    const float* b_hh_l0  = (const float*)d_in[6];
    const float* w_ih_l0r = (const float*)d_in[7];
    const float* w_hh_l0r = (const float*)d_in[8];
    const float* b_ih_l0r = (const float*)d_in[9];
    const float* b_hh_l0r = (const float*)d_in[10];
    const float* w_ih_l1  = (const float*)d_in[11];
    const float* w_hh_l1  = (const float*)d_in[12];
    const float* b_ih_l1  = (const float*)d_in[13];
    const float* b_hh_l1  = (const float*)d_in[14];
    const float* w_ih_l1r = (const float*)d_in[15];
    const float* w_hh_l1r = (const float*)d_in[16];
    const float* b_ih_l1r = (const float*)d_in[17];
    const float* b_hh_l1r = (const float*)d_in[18];
    const float* lin_w    = (const float*)d_in[19];
    const float* lin_b    = (const float*)d_in[20];
    const float* crf_start = (const float*)d_in[21];
    const float* crf_end   = (const float*)d_in[22];
    const float* crf_trans = (const float*)d_in[23];
    float* out = (float*)d_out;

    __nv_bfloat16 *px0, *phs0, *phs1, *pw0f, *pw0b, *pw1f, *pw1b, *plw;
    float *ppf, *ppb, *pdm;
    cudaGetSymbolAddress((void**)&px0,  g_x0b);
    cudaGetSymbolAddress((void**)&ppf,  g_pre_f);
    cudaGetSymbolAddress((void**)&ppb,  g_pre_b);
    cudaGetSymbolAddress((void**)&phs0, g_hs0b);
    cudaGetSymbolAddress((void**)&phs1, g_hs1b);
    cudaGetSymbolAddress((void**)&pdm,  g_dummy);
    cudaGetSymbolAddress((void**)&pw0f, g_wih0f);
    cudaGetSymbolAddress((void**)&pw0b, g_wih0b);
    cudaGetSymbolAddress((void**)&pw1f, g_wih1f);
    cudaGetSymbolAddress((void**)&pw1b, g_wih1b);
    cudaGetSymbolAddress((void**)&plw,  g_linwb);

    const int SM64  = 2 * 128 * 64 * 2;    // 32KB
    const int SM128 = 2 * 128 * 128 * 2;   // 64KB
    cudaFuncSetAttribute(k_mma<64, false>,  cudaFuncAttributeMaxDynamicSharedMemorySize, SM64);
    cudaFuncSetAttribute(k_mma<128, false>, cudaFuncAttributeMaxDynamicSharedMemorySize, SM128);
    cudaFuncSetAttribute(k_mma<128, true>,  cudaFuncAttributeMaxDynamicSharedMemorySize, SM128);

    const int NROW = Bc * Tc;  // 131072
    const int NT = NROW / 128; // 1024 tiles

    // fused weight conversions + embedding + CRF prep (no inter-deps)
    k_cvt5<<<(114688 + 255) / 256, 256>>>(w_ih_l0, w_ih_l0r, w_ih_l1, w_ih_l1r, lin_w);
    k_embed<<<(Bc * Tc * Ec / 8 + 255) / 256, 256>>>(x, emb);
    k_prep<<<Bc + 64, 256>>>(x, crf_trans);

    // layer 0 pre-activations (K=64, Gout=256): fwd+bwd fused via gridDim.z
    k_mma<64, false><<<dim3(NT, 2, 2), 256, SM64>>>(
        px0, pw0f, pw0b, b_ih_l0, b_ih_l0r, b_hh_l0, b_hh_l0r, ppf, ppb, Gc);
    k_lstm<<<dim3(Bc / Mb, 2), 128>>>(ppf, ppb, w_hh_l0, w_hh_l0r, phs0);

    // layer 1 pre-activations (K=128, Gout=256): fwd+bwd fused
    k_mma<128, false><<<dim3(NT, 2, 2), 256, SM128>>>(
        phs0, pw1f, pw1b, b_ih_l1, b_ih_l1r, b_hh_l1, b_hh_l1r, ppf, ppb, Gc);
    k_lstm<<<dim3(Bc / Mb, 2), 128>>>(ppf, ppb, w_hh_l1, w_hh_l1r, phs1);

    // emissions (K=128, Gout=128): writes only eem/emmax
    k_mma<128, true><<<dim3(NT, 1, 1), 256, SM128>>>(
        phs1, plw, plw, lin_b, lin_b, nullptr, nullptr, pdm, pdm, Vc);

    // CRF (M in registers)
    k_crf<<<Bc, 256>>>(crf_start, crf_end);
    k_score<<<Bc / 8, 256>>>(tags, crf_trans, crf_start, crf_end);
    k_final<<<1, 512>>>(out);
}

// round 16
// speedup vs baseline: 1.1501x; 1.0013x over previous
#include <cuda_runtime.h>
#include <cuda_bf16.h>
#include <cstdint>

#define Bc 512
#define Tc 256
#define Vc 128
#define Ec 64
#define Hc 64
#define Gc 256  // 4*H
#define Mb 4    // batches per LSTM CTA

// ---------------- scratch (static device globals; no allocation) ----------------
__device__ float g_pre_f[(size_t)Bc*Tc*Gc];
__device__ float g_pre_b[(size_t)Bc*Tc*Gc];
__device__ __nv_bfloat16 g_hs0b[(size_t)Bc*Tc*2*Hc];
__device__ __nv_bfloat16 g_hs1b[(size_t)Bc*Tc*2*Hc];
__device__ float g_eem  [(size_t)Bc*Tc*Vc];
__device__ float g_emmax[Bc*Tc];
__device__ float g_MexpT[Vc*Vc];
__device__ int   g_len  [Bc];
__device__ float g_scorev[Bc];
__device__ float g_part [Bc];
__device__ float g_dummy[(size_t)Bc*Tc*Vc];   // unused out target for emissions
// bf16 weights
__device__ __nv_bfloat16 g_wih0f[Gc*Ec];
__device__ __nv_bfloat16 g_wih0b[Gc*Ec];
__device__ __nv_bfloat16 g_wih1f[Gc*2*Hc];
__device__ __nv_bfloat16 g_wih1b[Gc*2*Hc];
__device__ __nv_bfloat16 g_linwb[Vc*2*Hc];

// ---------------- helpers ----------------
__device__ __forceinline__ uint32_t smem_u32(const void* p) {
    uint32_t a;
    asm("{ .reg .u64 t; cvta.to.shared.u64 t, %1; cvt.u32.u64 %0, t; }" : "=r"(a) : "l"(p));
    return a;
}
__device__ __forceinline__ unsigned long long pk2(float x, float y) {
    unsigned long long r;
    asm("mov.b64 %0, {%1, %2};" : "=l"(r) : "f"(x), "f"(y));
    return r;
}
__device__ __forceinline__ unsigned long long ffma2(unsigned long long a,
                                                    unsigned long long b,
                                                    unsigned long long c) {
    unsigned long long d;
    asm("fma.rn.f32x2 %0, %1, %2, %3;" : "=l"(d) : "l"(a), "l"(b), "l"(c));
    return d;
}
__device__ __forceinline__ float2 unpk(unsigned long long v) {
    float2 r;
    asm("mov.b64 {%0, %1}, %2;" : "=f"(r.x), "=f"(r.y) : "l"(v));
    return r;
}
__device__ __forceinline__ float tanh_hw(float x) {
    float r;
    asm("tanh.approx.f32 %0, %1;" : "=f"(r) : "f"(x));
    return r;
}
__device__ __forceinline__ float sigmoid_hw(float x) {
    return fmaf(0.5f, tanh_hw(0.5f * x), 0.5f);
}
__device__ __forceinline__ void ldmx4(uint32_t* r, uint32_t addr) {
    asm volatile("ldmatrix.sync.aligned.m8n8.x4.shared.b16 {%0,%1,%2,%3}, [%4];"
                 : "=r"(r[0]), "=r"(r[1]), "=r"(r[2]), "=r"(r[3]) : "r"(addr));
}
__device__ __forceinline__ void mma16816(float* c, const uint32_t* a, uint32_t b0, uint32_t b1) {
    asm volatile(
        "mma.sync.aligned.m16n8k16.row.col.f32.bf16.bf16.f32 "
        "{%0,%1,%2,%3}, {%4,%5,%6,%7}, {%8,%9}, {%0,%1,%2,%3};"
        : "+f"(c[0]), "+f"(c[1]), "+f"(c[2]), "+f"(c[3])
        : "r"(a[0]), "r"(a[1]), "r"(a[2]), "r"(a[3]), "r"(b0), "r"(b1));
}
__device__ __forceinline__ uint4 pack8bf16(float4 v0, float4 v1) {
    __nv_bfloat16 o[8];
    o[0] = __float2bfloat16(v0.x); o[1] = __float2bfloat16(v0.y);
    o[2] = __float2bfloat16(v0.z); o[3] = __float2bfloat16(v0.w);
    o[4] = __float2bfloat16(v1.x); o[5] = __float2bfloat16(v1.y);
    o[6] = __float2bfloat16(v1.z); o[7] = __float2bfloat16(v1.w);
    return *(uint4*)o;
}

// ---------------- fused prep: weight cvt (blk<448) + seq lengths + exp(trans)^T ----
__global__ void k_prep1(const float* __restrict__ s0, const float* __restrict__ s1,
                        const float* __restrict__ s2, const float* __restrict__ s3,
                        const float* __restrict__ s4,
                        const int* __restrict__ x, const float* __restrict__ trans) {
    int blk = blockIdx.x;
    if (blk < 448) {
        int i = blk * 256 + threadIdx.x;
        if (i < 16384)            g_wih0f[i] = __float2bfloat16(s0[i]);
        else if (i < 32768)       g_wih0b[i - 16384] = __float2bfloat16(s1[i - 16384]);
        else if (i < 65536)       g_wih1f[i - 32768] = __float2bfloat16(s2[i - 32768]);
        else if (i < 98304)       g_wih1b[i - 65536] = __float2bfloat16(s3[i - 65536]);
        else if (i < 114688)      g_linwb[i - 98304] = __float2bfloat16(s4[i - 98304]);
    } else if (blk < 448 + Bc) {
        int b = blk - 448;
        __shared__ int red[256];
        int tid = threadIdx.x;
        red[tid] = (x[b * Tc + tid] != 0) ? 1 : 0;
        __syncthreads();
        for (int s = 128; s; s >>= 1) {
            if (tid < s) red[tid] += red[tid + s];
            __syncthreads();
        }
        if (tid == 0) g_len[b] = red[0];
    } else {
        int idx = (blk - 448 - Bc) * 256 + threadIdx.x;
        if (idx < Vc * Vc) {
            int j = idx >> 7, i = idx & 127;
            g_MexpT[idx] = __expf(trans[i * Vc + j]);
        }
    }
}

// ---------------- HMMA GEMM: out[r, n] = sum_k A[r,k]*W[n,k] + bias ----------------
// blockIdx.z selects the (W, bias, out) set. EMEXP: write only eem/emmax.
// GATHER: A comes from emb[x[row]] (fp32 -> bf16 inline); A ptr unused.
template <int K, bool EMEXP, bool GATHER>
__global__ __launch_bounds__(256) void k_mma(const __nv_bfloat16* __restrict__ A,
                                             const int* __restrict__ xg,
                                             const float* __restrict__ embg,
                                             const __nv_bfloat16* __restrict__ Wf,
                                             const __nv_bfloat16* __restrict__ Wb,
                                             const float* __restrict__ b1f,
                                             const float* __restrict__ b1b,
                                             const float* __restrict__ b2f,
                                             const float* __restrict__ b2b,
                                             float* __restrict__ outf,
                                             float* __restrict__ outb, int Gout) {
    constexpr int VPR   = K / 8;
    constexpr int TILEB = 128 * K * 2;
    constexpr int NKS   = K / 16;

    extern __shared__ char sm[];
    __shared__ float bias[128];
    __shared__ float smp[128][4];

    const __nv_bfloat16* W = blockIdx.z ? Wb : Wf;
    const float* b1 = blockIdx.z ? b1b : b1f;
    const float* b2 = blockIdx.z ? b2b : b2f;
    float* out = blockIdx.z ? outb : outf;

    uint32_t sA = smem_u32(sm);
    uint32_t sB = sA + TILEB;

    int tid = threadIdx.x, wid = tid >> 5, lane = tid & 31;
    size_t row0 = (size_t)blockIdx.x * 128;
    int    col0 = blockIdx.y * 128;

    if (tid < 128) bias[tid] = b1[col0 + tid] + (b2 ? b2[col0 + tid] : 0.f);

    {
        char* smc = sm;
        if (GATHER) {
            // A tile gathered from embedding (K == Ec == 64, VPR == 8)
#pragma unroll 4
            for (int v = tid; v < 128 * VPR; v += 256) {
                int row = v / VPR, ck = v % VPR;
                int tok = xg[row0 + row];
                const float4* src = (const float4*)(embg + (size_t)tok * Ec + ck * 8);
                uint4 packed = pack8bf16(src[0], src[1]);
                int swb = ((ck & ~7) | ((ck ^ row) & 7)) * 16;
                *(uint4*)(smc + row * (2 * K) + swb) = packed;
            }
        } else {
            const uint4* Ag = (const uint4*)(A + row0 * K);
#pragma unroll 4
            for (int v = tid; v < 128 * VPR; v += 256) {
                int row = v / VPR, ck = v % VPR;
                int swb = ((ck & ~7) | ((ck ^ row) & 7)) * 16;
                *(uint4*)(smc + row * (2 * K) + swb) = Ag[v];
            }
        }
        const uint4* Wg = (const uint4*)(W + (size_t)col0 * K);
#pragma unroll 4
        for (int v = tid; v < 128 * VPR; v += 256) {
            int row = v / VPR, ck = v % VPR;
            int swb = ((ck & ~7) | ((ck ^ row) & 7)) * 16;
            *(uint4*)(smc + TILEB + row * (2 * K) + swb) = Wg[v];
        }
    }
    __syncthreads();

    int warp_m = wid & 1, warp_n = wid >> 1;
    int l7 = lane & 7;

    int rowA = warp_m * 64 + l7 + ((lane >> 3) & 1) * 8;
    int ckoffA = (lane >> 4) & 1;
    int rowB = warp_n * 32 + l7 + ((lane >> 4) & 1) * 8;
    int ckoffB = (lane >> 3) & 1;

    uint32_t aAbase = sA + rowA * (2 * K);
    uint32_t aBbase = sB + rowB * (2 * K);

    float acc[4][4][4];
#pragma unroll
    for (int mi = 0; mi < 4; mi++)
#pragma unroll
        for (int ni = 0; ni < 4; ni++)
#pragma unroll
            for (int e = 0; e < 4; e++) acc[mi][ni][e] = 0.f;

#pragma unroll
    for (int ks = 0; ks < NKS; ks++) {
        int xA = ks * 2 + ckoffA;
        int xB = ks * 2 + ckoffB;
        uint32_t swbA = (uint32_t)(((xA & ~7) | ((xA ^ l7) & 7)) * 16);
        uint32_t swbB = (uint32_t)(((xB & ~7) | ((xB ^ l7) & 7)) * 16);

        uint32_t afr[4][4];
#pragma unroll
        for (int mi = 0; mi < 4; mi++)
            ldmx4(afr[mi], aAbase + (uint32_t)(mi * 16 * 2 * K) + swbA);

        uint32_t bfr[2][4];
#pragma unroll
        for (int nb = 0; nb < 2; nb++)
            ldmx4(bfr[nb], aBbase + (uint32_t)(nb * 16 * 2 * K) + swbB);

#pragma unroll
        for (int mi = 0; mi < 4; mi++)
#pragma unroll
            for (int ni = 0; ni < 4; ni++)
                mma16816(acc[mi][ni], afr[mi],
                         bfr[ni >> 1][(ni & 1) * 2], bfr[ni >> 1][(ni & 1) * 2 + 1]);
    }

    int mrow = warp_m * 64 + (lane >> 2);
    int ncol = warp_n * 32 + (lane & 3) * 2;
    float lm[4][2];
#pragma unroll
    for (int mi = 0; mi < 4; mi++) { lm[mi][0] = -1e30f; lm[mi][1] = -1e30f; }

#pragma unroll
    for (int mi = 0; mi < 4; mi++) {
#pragma unroll
        for (int ni = 0; ni < 4; ni++) {
            int bc = ncol + ni * 8;
            float bx = bias[bc], by = bias[bc + 1];
            float2 v0 = make_float2(acc[mi][ni][0] + bx, acc[mi][ni][1] + by);
            float2 v1 = make_float2(acc[mi][ni][2] + bx, acc[mi][ni][3] + by);
            if (!EMEXP) {
                size_t r0g = (row0 + mrow + mi * 16) * (size_t)Gout + col0 + bc;
                size_t r1g = r0g + 8 * (size_t)Gout;
                *(float2*)(out + r0g) = v0;
                *(float2*)(out + r1g) = v1;
            } else {
                lm[mi][0] = fmaxf(lm[mi][0], fmaxf(v0.x, v0.y));
                lm[mi][1] = fmaxf(lm[mi][1], fmaxf(v1.x, v1.y));
            }
        }
    }

    if (EMEXP) {
#pragma unroll
        for (int mi = 0; mi < 4; mi++)
#pragma unroll
            for (int h = 0; h < 2; h++) {
                lm[mi][h] = fmaxf(lm[mi][h], __shfl_xor_sync(0xffffffffu, lm[mi][h], 1));
                lm[mi][h] = fmaxf(lm[mi][h], __shfl_xor_sync(0xffffffffu, lm[mi][h], 2));
            }
        if ((lane & 3) == 0) {
#pragma unroll
            for (int mi = 0; mi < 4; mi++)
#pragma unroll
                for (int h = 0; h < 2; h++) {
                    int r128 = warp_m * 64 + (lane >> 2) + mi * 16 + h * 8;
                    smp[r128][warp_n] = lm[mi][h];
                }
        }
        __syncthreads();
#pragma unroll
        for (int mi = 0; mi < 4; mi++) {
#pragma unroll
            for (int h = 0; h < 2; h++) {
                int r128 = warp_m * 64 + (lane >> 2) + mi * 16 + h * 8;
                float rm = fmaxf(fmaxf(smp[r128][0], smp[r128][1]),
                                 fmaxf(smp[r128][2], smp[r128][3]));
                size_t rg = row0 + r128;
#pragma unroll
                for (int ni = 0; ni < 4; ni++) {
                    int bc = ncol + ni * 8;
                    float bx = bias[bc], by = bias[bc + 1];
                    float ex = __expf(acc[mi][ni][2 * h + 0] + bx - rm);
                    float ey = __expf(acc[mi][ni][2 * h + 1] + by - rm);
                    *(float2*)(&g_eem[rg * Vc + bc]) = make_float2(ex, ey);
                }
                if (warp_n == 0 && (lane & 3) == 0) g_emmax[rg] = rm;
            }
        }
    }
}

// ---------------- LSTM recurrence: 128 threads, 2 gate rows per thread, Mb=4 ----
__global__ __launch_bounds__(128, 2) void k_lstm(const float* __restrict__ pre_f,
                                                 const float* __restrict__ pre_b,
                                                 const float* __restrict__ whh_f,
                                                 const float* __restrict__ whh_b,
                                                 __nv_bfloat16* __restrict__ hs) {
    int grp = blockIdx.x;
    int dir = blockIdx.y;
    const float* pre = dir ? pre_b : pre_f;
    const float* whh = dir ? whh_b : whh_f;
    int tt = threadIdx.x;
    int j2 = tt & 63, hf = tt >> 6;
    int rA = tt;
    int rB = rA + 128;
    int b0 = grp * Mb;
    int mh = hf * 2;

    unsigned long long wpA[32], wpB[32];
    {
        const float4* wa = (const float4*)(whh + (size_t)rA * 64);
        const float4* wb = (const float4*)(whh + (size_t)rB * 64);
#pragma unroll
        for (int i = 0; i < 16; i++) {
            float4 va = wa[i], vb = wb[i];
            wpA[2 * i]     = pk2(va.x, va.y);
            wpA[2 * i + 1] = pk2(va.z, va.w);
            wpB[2 * i]     = pk2(vb.x, vb.y);
            wpB[2 * i + 1] = pk2(vb.z, vb.w);
        }
    }

    __shared__ __align__(16) float h_sh[Mb][64];
    __shared__ float acts[4][2][64];

    float c[2] = {0.f, 0.f};
    if (tt < Mb * 16) ((float4*)h_sh)[tt] = make_float4(0.f, 0.f, 0.f, 0.f);
    __syncthreads();

    int t0 = dir ? (Tc - 1) : 0;
    float pnA[Mb], pnB[Mb];
#pragma unroll
    for (int m = 0; m < Mb; m++) {
        size_t base = ((size_t)(b0 + m) * Tc + t0) * Gc;
        pnA[m] = __ldcs(pre + base + rA);
        pnB[m] = __ldcs(pre + base + rB);
    }

    for (int s = 0; s < Tc; s++) {
        int t = dir ? (Tc - 1 - s) : s;
        float pcA[Mb], pcB[Mb];
#pragma unroll
        for (int m = 0; m < Mb; m++) { pcA[m] = pnA[m]; pcB[m] = pnB[m]; }
        if (s + 1 < Tc) {
            int tn = dir ? (Tc - 2 - s) : (s + 1);
#pragma unroll
            for (int m = 0; m < Mb; m++) {
                size_t base = ((size_t)(b0 + m) * Tc + tn) * Gc;
                pnA[m] = __ldcs(pre + base + rA);
                pnB[m] = __ldcs(pre + base + rB);
            }
        }

        float avA[Mb], avB[Mb];
#pragma unroll
        for (int m = 0; m < Mb; m++) {
            unsigned long long a0 = 0ull, a1 = 0ull, b0a = 0ull, b1a = 0ull;
            const ulonglong2* hp = (const ulonglong2*)h_sh[m];
#pragma unroll
            for (int i = 0; i < 16; i++) {
                ulonglong2 hv = hp[i];
                a0  = ffma2(wpA[2 * i],     hv.x, a0);
                a1  = ffma2(wpA[2 * i + 1], hv.y, a1);
                b0a = ffma2(wpB[2 * i],     hv.x, b0a);
                b1a = ffma2(wpB[2 * i + 1], hv.y, b1a);
            }
            float2 pa0 = unpk(a0), pa1 = unpk(a1);
            float2 pb0 = unpk(b0a), pb1 = unpk(b1a);
            avA[m] = pcA[m] + ((pa0.x + pa0.y) + (pa1.x + pa1.y));
            avB[m] = pcB[m] + ((pb0.x + pb0.y) + (pb1.x + pb1.y));
        }

        float actA[Mb], actB[Mb];
        if (hf == 0) {
#pragma unroll
            for (int m = 0; m < Mb; m++) {
                actA[m] = sigmoid_hw(avA[m]);
                actB[m] = tanh_hw(avB[m]);
            }
            acts[0][0][j2] = actA[2]; acts[0][1][j2] = actA[3];
            acts[2][0][j2] = actB[2]; acts[2][1][j2] = actB[3];
        } else {
#pragma unroll
            for (int m = 0; m < Mb; m++) {
                actA[m] = sigmoid_hw(avA[m]);
                actB[m] = sigmoid_hw(avB[m]);
            }
            acts[1][0][j2] = actA[0]; acts[1][1][j2] = actA[1];
            acts[3][0][j2] = actB[0]; acts[3][1][j2] = actB[1];
        }
        __syncthreads();

#pragma unroll
        for (int mm = 0; mm < 2; mm++) {
            int m = mh + mm;
            float i_, f_, gg, o_;
            if (hf == 0) {
                i_ = actA[m]; gg = actB[m];
                f_ = acts[1][mm][j2]; o_ = acts[3][mm][j2];
            } else {
                f_ = actA[m]; o_ = actB[m];
                i_ = acts[0][mm][j2]; gg = acts[2][mm][j2];
            }
            c[mm] = f_ * c[mm] + i_ * gg;
            float h = o_ * tanh_hw(c[mm]);
            h_sh[m][j2] = h;
            hs[((size_t)(b0 + m) * Tc + t) * 128 + dir * 64 + j2] = __float2bfloat16(h);
        }
        __syncthreads();
    }
}

// ---------------- CRF forward (M in registers, 256 threads) ----------------
__device__ __forceinline__ float bmax256(float v, float* red) {
#pragma unroll
    for (int o = 16; o; o >>= 1) v = fmaxf(v, __shfl_xor_sync(0xffffffffu, v, o));
    __syncthreads();
    if ((threadIdx.x & 31) == 0) red[threadIdx.x >> 5] = v;
    __syncthreads();
    float m = fmaxf(fmaxf(fmaxf(red[0], red[1]), fmaxf(red[2], red[3])),
                    fmaxf(fmaxf(red[4], red[5]), fmaxf(red[6], red[7])));
    return m;
}
__device__ __forceinline__ float bsum256(float v, float* red) {
#pragma unroll
    for (int o = 16; o; o >>= 1) v += __shfl_xor_sync(0xffffffffu, v, o);
    __syncthreads();
    if ((threadIdx.x & 31) == 0) red[threadIdx.x >> 5] = v;
    __syncthreads();
    return ((red[0] + red[1]) + (red[2] + red[3])) +
           ((red[4] + red[5]) + (red[6] + red[7]));
}

__global__ __launch_bounds__(256) void k_crf(const float* __restrict__ startv,
                                             const float* __restrict__ endv) {
    __shared__ __align__(16) float a_sh[2][Vc];
    __shared__ float red[8];
    int b = blockIdx.x;
    int tt = threadIdx.x;
    int w = tt >> 5, l = tt & 31;
    int j = w * 16 + (l & 15);
    int half = l >> 4;

    unsigned long long Mreg[32];
    {
        const float4* msrc = (const float4*)(g_MexpT + (size_t)j * Vc + half * 64);
#pragma unroll
        for (int i = 0; i < 16; i++) {
            float4 v = msrc[i];
            Mreg[2 * i]     = pk2(v.x, v.y);
            Mreg[2 * i + 1] = pk2(v.z, v.w);
        }
    }

    int len = g_len[b];
    float al0 = startv[j] + g_emmax[b * Tc] + __logf(g_eem[(size_t)b * Tc * Vc + j]);
    float m = bmax256(al0, red);
    if (half == 0) a_sh[0][j] = __expf(al0 - m);
    float off = m;
    __syncthreads();

    const float LOG128 = 4.852030263919617f;
    int cur = 0;

    for (int t = 1; t < len; t++) {
        float ee  = g_eem[((size_t)b * Tc + t) * Vc + j];
        float emx = g_emmax[b * Tc + t];
        unsigned long long s0 = 0ull, s1 = 0ull;
        const ulonglong2* ap = (const ulonglong2*)(a_sh[cur] + half * 64);
#pragma unroll
        for (int i = 0; i < 16; i += 2) {
            ulonglong2 a0v = ap[i], a1v = ap[i + 1];
            s0 = ffma2(a0v.x, Mreg[2 * i],     s0);
            s1 = ffma2(a0v.y, Mreg[2 * i + 1], s1);
            s0 = ffma2(a1v.x, Mreg[2 * i + 2], s0);
            s1 = ffma2(a1v.y, Mreg[2 * i + 3], s1);
        }
        float2 p0 = unpk(s0), p1 = unpk(s1);
        float part = (p0.x + p0.y) + (p1.x + p1.y);
        part += __shfl_xor_sync(0xffffffffu, part, 16);
        float v = part * ee;
        if ((t & 15) == 0) {
            float vmax = bmax256(v, red);
            if (half == 0) a_sh[cur ^ 1][j] = v * (1.f / vmax);
            off += emx + __logf(vmax);
        } else {
            if (half == 0) a_sh[cur ^ 1][j] = v * 0.0078125f;
            off += emx + LOG128;
        }
        cur ^= 1;
        __syncthreads();
    }

    float term = (half == 0) ? a_sh[cur][j] * __expf(endv[j]) : 0.f;
    float ssum = bsum256(term, red);
    if (tt == 0) g_part[b] = off + __logf(ssum);
}

// ---------------- gold-path score (em reconstructed from eem/emmax) ----------------
__global__ void k_score(const int* __restrict__ tags, const float* __restrict__ trans,
                        const float* __restrict__ startv, const float* __restrict__ endv) {
    int gw = (blockIdx.x * blockDim.x + threadIdx.x) >> 5;
    int lane = threadIdx.x & 31;
    if (gw >= Bc) return;
    int b = gw;
    int len = g_len[b];
    float s = 0.f;
    for (int t = 1 + lane; t < len; t += 32) {
        int tp  = tags[b * Tc + t - 1];
        int tcu = tags[b * Tc + t];
        float em = g_emmax[b * Tc + t] + __logf(g_eem[((size_t)b * Tc + t) * Vc + tcu]);
        s += trans[tp * Vc + tcu] + em;
    }
#pragma unroll
    for (int o = 16; o; o >>= 1) s += __shfl_xor_sync(0xffffffffu, s, o);
    if (lane == 0) {
        int t0 = tags[b * Tc];
        int tl = tags[b * Tc + len - 1];
        float em0 = g_emmax[b * Tc] + __logf(g_eem[(size_t)b * Tc * Vc + t0]);
        s += startv[t0] + em0 + endv[tl];
        g_scorev[b] = s;
    }
}

// ---------------- final reduction ----------------
__global__ void k_final(float* __restrict__ out) {
    __shared__ float red[512];
    int t = threadIdx.x;
    red[t] = g_scorev[t] - g_part[t];
    __syncthreads();
    for (int s = 256; s; s >>= 1) {
        if (t < s) red[t] += red[t + s];
        __syncthreads();
    }
    if (t == 0) out[0] = -red[0] * (1.f / Bc);
}

// ---------------- host launcher ----------------
extern "C" void kernel_launch(void* const* d_in, const int* in_sizes, int n_in,
                              void* d_out, int out_size) {
    const int*   x        = (const int*)d_in[0];
    const int*   tags     = (const int*)d_in[1];
    const float* emb      = (const float*)d_in[2];
    const float* w_ih_l0  = (const float*)d_in[3];
    const float* w_hh_l0  = (const float*)d_in[4];
    const float* b_ih_l0  = (const float*)d_in[5];
    const float* b_hh_l0  = (const float*)d_in[6];
    const float* w_ih_l0r = (const float*)d_in[7];
    const float* w_hh_l0r = (const float*)d_in[8];
    const float* b_ih_l0r = (const float*)d_in[9];
    const float* b_hh_l0r = (const float*)d_in[10];
    const float* w_ih_l1  = (const float*)d_in[11];
    const float* w_hh_l1  = (const float*)d_in[12];
    const float* b_ih_l1  = (const float*)d_in[13];
    const float* b_hh_l1  = (const float*)d_in[14];
    const float* w_ih_l1r = (const float*)d_in[15];
    const float* w_hh_l1r = (const float*)d_in[16];
    const float* b_ih_l1r = (const float*)d_in[17];
    const float* b_hh_l1r = (const float*)d_in[18];
    const float* lin_w    = (const float*)d_in[19];
    const float* lin_b    = (const float*)d_in[20];
    const float* crf_start = (const float*)d_in[21];
    const float* crf_end   = (const float*)d_in[22];
    const float* crf_trans = (const float*)d_in[23];
    float* out = (float*)d_out;

    __nv_bfloat16 *phs0, *phs1, *pw0f, *pw0b, *pw1f, *pw1b, *plw;
    float *ppf, *ppb, *pdm;
    cudaGetSymbolAddress((void**)&ppf,  g_pre_f);
    cudaGetSymbolAddress((void**)&ppb,  g_pre_b);
    cudaGetSymbolAddress((void**)&phs0, g_hs0b);
    cudaGetSymbolAddress((void**)&phs1, g_hs1b);
    cudaGetSymbolAddress((void**)&pdm,  g_dummy);
    cudaGetSymbolAddress((void**)&pw0f, g_wih0f);
    cudaGetSymbolAddress((void**)&pw0b, g_wih0b);
    cudaGetSymbolAddress((void**)&pw1f, g_wih1f);
    cudaGetSymbolAddress((void**)&pw1b, g_wih1b);
    cudaGetSymbolAddress((void**)&plw,  g_linwb);

    const int SM64  = 2 * 128 * 64 * 2;    // 32KB
    const int SM128 = 2 * 128 * 128 * 2;   // 64KB
    cudaFuncSetAttribute((const void*)k_mma<64, false, true>,
                         cudaFuncAttributeMaxDynamicSharedMemorySize, SM64);
    cudaFuncSetAttribute((const void*)k_mma<128, false, false>,
                         cudaFuncAttributeMaxDynamicSharedMemorySize, SM128);
    cudaFuncSetAttribute((const void*)k_mma<128, true, false>,
                         cudaFuncAttributeMaxDynamicSharedMemorySize, SM128);

    const int NROW = Bc * Tc;  // 131072
    const int NT = NROW / 128; // 1024 tiles

    // fused prep: weight cvt + lengths + exp(trans)^T (one launch)
    k_prep1<<<448 + Bc + 64, 256>>>(w_ih_l0, w_ih_l0r, w_ih_l1, w_ih_l1r, lin_w,
                                    x, crf_trans);

    // layer 0 pre-activations (K=64, Gout=256): embedding gathered in-GEMM
    k_mma<64, false, true><<<dim3(NT, 2, 2), 256, SM64>>>(
        nullptr, x, emb, pw0f, pw0b,
        b_ih_l0, b_ih_l0r, b_hh_l0, b_hh_l0r, ppf, ppb, Gc);
    k_lstm<<<dim3(Bc / Mb, 2), 128>>>(ppf, ppb, w_hh_l0, w_hh_l0r, phs0);

    // layer 1 pre-activations (K=128, Gout=256): fwd+bwd fused
    k_mma<128, false, false><<<dim3(NT, 2, 2), 256, SM128>>>(
        phs0, nullptr, nullptr, pw1f, pw1b,
        b_ih_l1, b_ih_l1r, b_hh_l1, b_hh_l1r, ppf, ppb, Gc);
    k_lstm<<<dim3(Bc / Mb, 2), 128>>>(ppf, ppb, w_hh_l1, w_hh_l1r, phs1);

    // emissions (K=128, Gout=128): writes only eem/emmax
    k_mma<128, true, false><<<dim3(NT, 1, 1), 256, SM128>>>(
        phs1, nullptr, nullptr, plw, plw,
        lin_b, lin_b, nullptr, nullptr, pdm, pdm, Vc);

    // CRF (M in registers)
    k_crf<<<Bc, 256>>>(crf_start, crf_end);
    k_score<<<Bc / 8, 256>>>(tags, crf_trans, crf_start, crf_end);
    k_final<<<1, 512>>>(out);
}

// round 17
// speedup vs baseline: 1.1837x; 1.0292x over previous
#include <cuda_runtime.h>
#include <cuda_bf16.h>
#include <cstdint>

#define Bc 512
#define Tc 256
#define Vc 128
#define Ec 64
#define Hc 64
#define Gc 256  // 4*H
#define Mb 4    // batches per LSTM CTA

// ---------------- scratch (static device globals; no allocation) ----------------
__device__ float g_pre_f[(size_t)Bc*Tc*Gc];
__device__ float g_pre_b[(size_t)Bc*Tc*Gc];
__device__ __nv_bfloat16 g_hs0b[(size_t)Bc*Tc*2*Hc];
__device__ __nv_bfloat16 g_hs1b[(size_t)Bc*Tc*2*Hc];
__device__ float g_eem  [(size_t)Bc*Tc*Vc];
__device__ float g_emmax[Bc*Tc];
__device__ float g_MexpT[Vc*Vc];
__device__ int   g_len  [Bc];
__device__ float g_scorev[Bc];
__device__ float g_part [Bc];
__device__ float g_dummy[(size_t)Bc*Tc*Vc];   // unused out target for emissions
// bf16 weights
__device__ __nv_bfloat16 g_wih0f[Gc*Ec];
__device__ __nv_bfloat16 g_wih0b[Gc*Ec];
__device__ __nv_bfloat16 g_wih1f[Gc*2*Hc];
__device__ __nv_bfloat16 g_wih1b[Gc*2*Hc];
__device__ __nv_bfloat16 g_linwb[Vc*2*Hc];

// ---------------- helpers ----------------
__device__ __forceinline__ uint32_t smem_u32(const void* p) {
    uint32_t a;
    asm("{ .reg .u64 t; cvta.to.shared.u64 t, %1; cvt.u32.u64 %0, t; }" : "=r"(a) : "l"(p));
    return a;
}
__device__ __forceinline__ unsigned long long pk2(float x, float y) {
    unsigned long long r;
    asm("mov.b64 %0, {%1, %2};" : "=l"(r) : "f"(x), "f"(y));
    return r;
}
__device__ __forceinline__ unsigned long long ffma2(unsigned long long a,
                                                    unsigned long long b,
                                                    unsigned long long c) {
    unsigned long long d;
    asm("fma.rn.f32x2 %0, %1, %2, %3;" : "=l"(d) : "l"(a), "l"(b), "l"(c));
    return d;
}
__device__ __forceinline__ float2 unpk(unsigned long long v) {
    float2 r;
    asm("mov.b64 {%0, %1}, %2;" : "=f"(r.x), "=f"(r.y) : "l"(v));
    return r;
}
__device__ __forceinline__ float tanh_hw(float x) {
    float r;
    asm("tanh.approx.f32 %0, %1;" : "=f"(r) : "f"(x));
    return r;
}
__device__ __forceinline__ float sigmoid_hw(float x) {
    return fmaf(0.5f, tanh_hw(0.5f * x), 0.5f);
}
__device__ __forceinline__ void ldmx4(uint32_t* r, uint32_t addr) {
    asm volatile("ldmatrix.sync.aligned.m8n8.x4.shared.b16 {%0,%1,%2,%3}, [%4];"
                 : "=r"(r[0]), "=r"(r[1]), "=r"(r[2]), "=r"(r[3]) : "r"(addr));
}
__device__ __forceinline__ void mma16816(float* c, const uint32_t* a, uint32_t b0, uint32_t b1) {
    asm volatile(
        "mma.sync.aligned.m16n8k16.row.col.f32.bf16.bf16.f32 "
        "{%0,%1,%2,%3}, {%4,%5,%6,%7}, {%8,%9}, {%0,%1,%2,%3};"
        : "+f"(c[0]), "+f"(c[1]), "+f"(c[2]), "+f"(c[3])
        : "r"(a[0]), "r"(a[1]), "r"(a[2]), "r"(a[3]), "r"(b0), "r"(b1));
}
__device__ __forceinline__ uint4 pack8bf16(float4 v0, float4 v1) {
    __nv_bfloat16 o[8];
    o[0] = __float2bfloat16(v0.x); o[1] = __float2bfloat16(v0.y);
    o[2] = __float2bfloat16(v0.z); o[3] = __float2bfloat16(v0.w);
    o[4] = __float2bfloat16(v1.x); o[5] = __float2bfloat16(v1.y);
    o[6] = __float2bfloat16(v1.z); o[7] = __float2bfloat16(v1.w);
    return *(uint4*)o;
}
#define CP_ASYNC16(dst, src) \
    asm volatile("cp.async.cg.shared.global [%0], [%1], 16;" \
                 :: "r"(dst), "l"(src) : "memory")
#define CP_COMMIT() asm volatile("cp.async.commit_group;" ::: "memory")
#define CP_WAIT0()  asm volatile("cp.async.wait_group 0;" ::: "memory")

// ---------------- fused prep: weight cvt (blk<448) + seq lengths + exp(trans)^T ----
__global__ void k_prep1(const float* __restrict__ s0, const float* __restrict__ s1,
                        const float* __restrict__ s2, const float* __restrict__ s3,
                        const float* __restrict__ s4,
                        const int* __restrict__ x, const float* __restrict__ trans) {
    int blk = blockIdx.x;
    if (blk < 448) {
        int i = blk * 256 + threadIdx.x;
        if (i < 16384)            g_wih0f[i] = __float2bfloat16(s0[i]);
        else if (i < 32768)       g_wih0b[i - 16384] = __float2bfloat16(s1[i - 16384]);
        else if (i < 65536)       g_wih1f[i - 32768] = __float2bfloat16(s2[i - 32768]);
        else if (i < 98304)       g_wih1b[i - 65536] = __float2bfloat16(s3[i - 65536]);
        else if (i < 114688)      g_linwb[i - 98304] = __float2bfloat16(s4[i - 98304]);
    } else if (blk < 448 + Bc) {
        int b = blk - 448;
        __shared__ int red[256];
        int tid = threadIdx.x;
        red[tid] = (x[b * Tc + tid] != 0) ? 1 : 0;
        __syncthreads();
        for (int s = 128; s; s >>= 1) {
            if (tid < s) red[tid] += red[tid + s];
            __syncthreads();
        }
        if (tid == 0) g_len[b] = red[0];
    } else {
        int idx = (blk - 448 - Bc) * 256 + threadIdx.x;
        if (idx < Vc * Vc) {
            int j = idx >> 7, i = idx & 127;
            g_MexpT[idx] = __expf(trans[i * Vc + j]);
        }
    }
}

// ---------------- HMMA GEMM: out[r, n] = sum_k A[r,k]*W[n,k] + bias ----------------
// blockIdx.z selects the (W, bias, out) set. EMEXP: write only eem/emmax.
// GATHER: A comes from emb[x[row]] (fp32 -> bf16 inline). Tile loads via cp.async.
template <int K, bool EMEXP, bool GATHER>
__global__ __launch_bounds__(256) void k_mma(const __nv_bfloat16* __restrict__ A,
                                             const int* __restrict__ xg,
                                             const float* __restrict__ embg,
                                             const __nv_bfloat16* __restrict__ Wf,
                                             const __nv_bfloat16* __restrict__ Wb,
                                             const float* __restrict__ b1f,
                                             const float* __restrict__ b1b,
                                             const float* __restrict__ b2f,
                                             const float* __restrict__ b2b,
                                             float* __restrict__ outf,
                                             float* __restrict__ outb, int Gout) {
    constexpr int VPR   = K / 8;
    constexpr int TILEB = 128 * K * 2;
    constexpr int NKS   = K / 16;

    extern __shared__ char sm[];
    __shared__ float bias[128];
    __shared__ float smp[128][4];

    const __nv_bfloat16* W = blockIdx.z ? Wb : Wf;
    const float* b1 = blockIdx.z ? b1b : b1f;
    const float* b2 = blockIdx.z ? b2b : b2f;
    float* out = blockIdx.z ? outb : outf;

    uint32_t sA = smem_u32(sm);
    uint32_t sB = sA + TILEB;

    int tid = threadIdx.x, wid = tid >> 5, lane = tid & 31;
    size_t row0 = (size_t)blockIdx.x * 128;
    int    col0 = blockIdx.y * 128;

    if (tid < 128) bias[tid] = b1[col0 + tid] + (b2 ? b2[col0 + tid] : 0.f);

    {
        // W tile via cp.async
        const uint4* Wg = (const uint4*)(W + (size_t)col0 * K);
#pragma unroll 4
        for (int v = tid; v < 128 * VPR; v += 256) {
            int row = v / VPR, ck = v % VPR;
            int swb = ((ck & ~7) | ((ck ^ row) & 7)) * 16;
            CP_ASYNC16(sB + row * (2 * K) + swb, Wg + v);
        }
        if (GATHER) {
            // A tile gathered from embedding (K == Ec == 64, VPR == 8)
            char* smc = sm;
#pragma unroll 4
            for (int v = tid; v < 128 * VPR; v += 256) {
                int row = v / VPR, ck = v % VPR;
                int tok = xg[row0 + row];
                const float4* src = (const float4*)(embg + (size_t)tok * Ec + ck * 8);
                uint4 packed = pack8bf16(src[0], src[1]);
                int swb = ((ck & ~7) | ((ck ^ row) & 7)) * 16;
                *(uint4*)(smc + row * (2 * K) + swb) = packed;
            }
        } else {
            const uint4* Ag = (const uint4*)(A + row0 * K);
#pragma unroll 4
            for (int v = tid; v < 128 * VPR; v += 256) {
                int row = v / VPR, ck = v % VPR;
                int swb = ((ck & ~7) | ((ck ^ row) & 7)) * 16;
                CP_ASYNC16(sA + row * (2 * K) + swb, Ag + v);
            }
        }
        CP_COMMIT();
        CP_WAIT0();
    }
    __syncthreads();

    int warp_m = wid & 1, warp_n = wid >> 1;
    int l7 = lane & 7;

    int rowA = warp_m * 64 + l7 + ((lane >> 3) & 1) * 8;
    int ckoffA = (lane >> 4) & 1;
    int rowB = warp_n * 32 + l7 + ((lane >> 4) & 1) * 8;
    int ckoffB = (lane >> 3) & 1;

    uint32_t aAbase = sA + rowA * (2 * K);
    uint32_t aBbase = sB + rowB * (2 * K);

    float acc[4][4][4];
#pragma unroll
    for (int mi = 0; mi < 4; mi++)
#pragma unroll
        for (int ni = 0; ni < 4; ni++)
#pragma unroll
            for (int e = 0; e < 4; e++) acc[mi][ni][e] = 0.f;

#pragma unroll
    for (int ks = 0; ks < NKS; ks++) {
        int xA = ks * 2 + ckoffA;
        int xB = ks * 2 + ckoffB;
        uint32_t swbA = (uint32_t)(((xA & ~7) | ((xA ^ l7) & 7)) * 16);
        uint32_t swbB = (uint32_t)(((xB & ~7) | ((xB ^ l7) & 7)) * 16);

        uint32_t afr[4][4];
#pragma unroll
        for (int mi = 0; mi < 4; mi++)
            ldmx4(afr[mi], aAbase + (uint32_t)(mi * 16 * 2 * K) + swbA);

        uint32_t bfr[2][4];
#pragma unroll
        for (int nb = 0; nb < 2; nb++)
            ldmx4(bfr[nb], aBbase + (uint32_t)(nb * 16 * 2 * K) + swbB);

#pragma unroll
        for (int mi = 0; mi < 4; mi++)
#pragma unroll
            for (int ni = 0; ni < 4; ni++)
                mma16816(acc[mi][ni], afr[mi],
                         bfr[ni >> 1][(ni & 1) * 2], bfr[ni >> 1][(ni & 1) * 2 + 1]);
    }

    int mrow = warp_m * 64 + (lane >> 2);
    int ncol = warp_n * 32 + (lane & 3) * 2;
    float lm[4][2];
#pragma unroll
    for (int mi = 0; mi < 4; mi++) { lm[mi][0] = -1e30f; lm[mi][1] = -1e30f; }

#pragma unroll
    for (int mi = 0; mi < 4; mi++) {
#pragma unroll
        for (int ni = 0; ni < 4; ni++) {
            int bc = ncol + ni * 8;
            float bx = bias[bc], by = bias[bc + 1];
            float2 v0 = make_float2(acc[mi][ni][0] + bx, acc[mi][ni][1] + by);
            float2 v1 = make_float2(acc[mi][ni][2] + bx, acc[mi][ni][3] + by);
            if (!EMEXP) {
                size_t r0g = (row0 + mrow + mi * 16) * (size_t)Gout + col0 + bc;
                size_t r1g = r0g + 8 * (size_t)Gout;
                *(float2*)(out + r0g) = v0;
                *(float2*)(out + r1g) = v1;
            } else {
                lm[mi][0] = fmaxf(lm[mi][0], fmaxf(v0.x, v0.y));
                lm[mi][1] = fmaxf(lm[mi][1], fmaxf(v1.x, v1.y));
            }
        }
    }

    if (EMEXP) {
#pragma unroll
        for (int mi = 0; mi < 4; mi++)
#pragma unroll
            for (int h = 0; h < 2; h++) {
                lm[mi][h] = fmaxf(lm[mi][h], __shfl_xor_sync(0xffffffffu, lm[mi][h], 1));
                lm[mi][h] = fmaxf(lm[mi][h], __shfl_xor_sync(0xffffffffu, lm[mi][h], 2));
            }
        if ((lane & 3) == 0) {
#pragma unroll
            for (int mi = 0; mi < 4; mi++)
#pragma unroll
                for (int h = 0; h < 2; h++) {
                    int r128 = warp_m * 64 + (lane >> 2) + mi * 16 + h * 8;
                    smp[r128][warp_n] = lm[mi][h];
                }
        }
        __syncthreads();
#pragma unroll
        for (int mi = 0; mi < 4; mi++) {
#pragma unroll
            for (int h = 0; h < 2; h++) {
                int r128 = warp_m * 64 + (lane >> 2) + mi * 16 + h * 8;
                float rm = fmaxf(fmaxf(smp[r128][0], smp[r128][1]),
                                 fmaxf(smp[r128][2], smp[r128][3]));
                size_t rg = row0 + r128;
#pragma unroll
                for (int ni = 0; ni < 4; ni++) {
                    int bc = ncol + ni * 8;
                    float bx = bias[bc], by = bias[bc + 1];
                    float ex = __expf(acc[mi][ni][2 * h + 0] + bx - rm);
                    float ey = __expf(acc[mi][ni][2 * h + 1] + by - rm);
                    *(float2*)(&g_eem[rg * Vc + bc]) = make_float2(ex, ey);
                }
                if (warp_n == 0 && (lane & 3) == 0) g_emmax[rg] = rm;
            }
        }
    }
}

// ---------------- LSTM recurrence: 128 threads, 2 gate rows per thread, Mb=4 ----
__global__ __launch_bounds__(128, 2) void k_lstm(const float* __restrict__ pre_f,
                                                 const float* __restrict__ pre_b,
                                                 const float* __restrict__ whh_f,
                                                 const float* __restrict__ whh_b,
                                                 __nv_bfloat16* __restrict__ hs) {
    int grp = blockIdx.x;
    int dir = blockIdx.y;
    const float* pre = dir ? pre_b : pre_f;
    const float* whh = dir ? whh_b : whh_f;
    int tt = threadIdx.x;
    int j2 = tt & 63, hf = tt >> 6;
    int rA = tt;
    int rB = rA + 128;
    int b0 = grp * Mb;
    int mh = hf * 2;

    unsigned long long wpA[32], wpB[32];
    {
        const float4* wa = (const float4*)(whh + (size_t)rA * 64);
        const float4* wb = (const float4*)(whh + (size_t)rB * 64);
#pragma unroll
        for (int i = 0; i < 16; i++) {
            float4 va = wa[i], vb = wb[i];
            wpA[2 * i]     = pk2(va.x, va.y);
            wpA[2 * i + 1] = pk2(va.z, va.w);
            wpB[2 * i]     = pk2(vb.x, vb.y);
            wpB[2 * i + 1] = pk2(vb.z, vb.w);
        }
    }

    __shared__ __align__(16) float h_sh[Mb][64];
    __shared__ float acts[4][2][64];

    float c[2] = {0.f, 0.f};
    if (tt < Mb * 16) ((float4*)h_sh)[tt] = make_float4(0.f, 0.f, 0.f, 0.f);
    __syncthreads();

    int t0 = dir ? (Tc - 1) : 0;
    float pnA[Mb], pnB[Mb];
#pragma unroll
    for (int m = 0; m < Mb; m++) {
        size_t base = ((size_t)(b0 + m) * Tc + t0) * Gc;
        pnA[m] = __ldcs(pre + base + rA);
        pnB[m] = __ldcs(pre + base + rB);
    }

    for (int s = 0; s < Tc; s++) {
        int t = dir ? (Tc - 1 - s) : s;
        float pcA[Mb], pcB[Mb];
#pragma unroll
        for (int m = 0; m < Mb; m++) { pcA[m] = pnA[m]; pcB[m] = pnB[m]; }
        if (s + 1 < Tc) {
            int tn = dir ? (Tc - 2 - s) : (s + 1);
#pragma unroll
            for (int m = 0; m < Mb; m++) {
                size_t base = ((size_t)(b0 + m) * Tc + tn) * Gc;
                pnA[m] = __ldcs(pre + base + rA);
                pnB[m] = __ldcs(pre + base + rB);
            }
        }

        float avA[Mb], avB[Mb];
#pragma unroll
        for (int m = 0; m < Mb; m++) {
            unsigned long long a0 = 0ull, a1 = 0ull, b0a = 0ull, b1a = 0ull;
            const ulonglong2* hp = (const ulonglong2*)h_sh[m];
#pragma unroll
            for (int i = 0; i < 16; i++) {
                ulonglong2 hv = hp[i];
                a0  = ffma2(wpA[2 * i],     hv.x, a0);
                a1  = ffma2(wpA[2 * i + 1], hv.y, a1);
                b0a = ffma2(wpB[2 * i],     hv.x, b0a);
                b1a = ffma2(wpB[2 * i + 1], hv.y, b1a);
            }
            float2 pa0 = unpk(a0), pa1 = unpk(a1);
            float2 pb0 = unpk(b0a), pb1 = unpk(b1a);
            avA[m] = pcA[m] + ((pa0.x + pa0.y) + (pa1.x + pa1.y));
            avB[m] = pcB[m] + ((pb0.x + pb0.y) + (pb1.x + pb1.y));
        }

        float actA[Mb], actB[Mb];
        if (hf == 0) {
#pragma unroll
            for (int m = 0; m < Mb; m++) {
                actA[m] = sigmoid_hw(avA[m]);
                actB[m] = tanh_hw(avB[m]);
            }
            acts[0][0][j2] = actA[2]; acts[0][1][j2] = actA[3];
            acts[2][0][j2] = actB[2]; acts[2][1][j2] = actB[3];
        } else {
#pragma unroll
            for (int m = 0; m < Mb; m++) {
                actA[m] = sigmoid_hw(avA[m]);
                actB[m] = sigmoid_hw(avB[m]);
            }
            acts[1][0][j2] = actA[0]; acts[1][1][j2] = actA[1];
            acts[3][0][j2] = actB[0]; acts[3][1][j2] = actB[1];
        }
        __syncthreads();

#pragma unroll
        for (int mm = 0; mm < 2; mm++) {
            int m = mh + mm;
            float i_, f_, gg, o_;
            if (hf == 0) {
                i_ = actA[m]; gg = actB[m];
                f_ = acts[1][mm][j2]; o_ = acts[3][mm][j2];
            } else {
                f_ = actA[m]; o_ = actB[m];
                i_ = acts[0][mm][j2]; gg = acts[2][mm][j2];
            }
            c[mm] = f_ * c[mm] + i_ * gg;
            float h = o_ * tanh_hw(c[mm]);
            h_sh[m][j2] = h;
            hs[((size_t)(b0 + m) * Tc + t) * 128 + dir * 64 + j2] = __float2bfloat16(h);
        }
        __syncthreads();
    }
}

// ---------------- CRF forward (M in registers, 256 threads) ----------------
__device__ __forceinline__ float bmax256(float v, float* red) {
#pragma unroll
    for (int o = 16; o; o >>= 1) v = fmaxf(v, __shfl_xor_sync(0xffffffffu, v, o));
    __syncthreads();
    if ((threadIdx.x & 31) == 0) red[threadIdx.x >> 5] = v;
    __syncthreads();
    float m = fmaxf(fmaxf(fmaxf(red[0], red[1]), fmaxf(red[2], red[3])),
                    fmaxf(fmaxf(red[4], red[5]), fmaxf(red[6], red[7])));
    return m;
}
__device__ __forceinline__ float bsum256(float v, float* red) {
#pragma unroll
    for (int o = 16; o; o >>= 1) v += __shfl_xor_sync(0xffffffffu, v, o);
    __syncthreads();
    if ((threadIdx.x & 31) == 0) red[threadIdx.x >> 5] = v;
    __syncthreads();
    return ((red[0] + red[1]) + (red[2] + red[3])) +
           ((red[4] + red[5]) + (red[6] + red[7]));
}

__global__ __launch_bounds__(256) void k_crf(const float* __restrict__ startv,
                                             const float* __restrict__ endv) {
    __shared__ __align__(16) float a_sh[2][Vc];
    __shared__ float red[8];
    int b = blockIdx.x;
    int tt = threadIdx.x;
    int w = tt >> 5, l = tt & 31;
    int j = w * 16 + (l & 15);
    int half = l >> 4;

    unsigned long long Mreg[32];
    {
        const float4* msrc = (const float4*)(g_MexpT + (size_t)j * Vc + half * 64);
#pragma unroll
        for (int i = 0; i < 16; i++) {
            float4 v = msrc[i];
            Mreg[2 * i]     = pk2(v.x, v.y);
            Mreg[2 * i + 1] = pk2(v.z, v.w);
        }
    }

    int len = g_len[b];
    float al0 = startv[j] + g_emmax[b * Tc] + __logf(g_eem[(size_t)b * Tc * Vc + j]);
    float m = bmax256(al0, red);
    if (half == 0) a_sh[0][j] = __expf(al0 - m);
    float off = m;
    __syncthreads();

    const float LOG128 = 4.852030263919617f;
    int cur = 0;

    for (int t = 1; t < len; t++) {
        float ee  = g_eem[((size_t)b * Tc + t) * Vc + j];
        float emx = g_emmax[b * Tc + t];
        unsigned long long s0 = 0ull, s1 = 0ull;
        const ulonglong2* ap = (const ulonglong2*)(a_sh[cur] + half * 64);
#pragma unroll
        for (int i = 0; i < 16; i += 2) {
            ulonglong2 a0v = ap[i], a1v = ap[i + 1];
            s0 = ffma2(a0v.x, Mreg[2 * i],     s0);
            s1 = ffma2(a0v.y, Mreg[2 * i + 1], s1);
            s0 = ffma2(a1v.x, Mreg[2 * i + 2], s0);
            s1 = ffma2(a1v.y, Mreg[2 * i + 3], s1);
        }
        float2 p0 = unpk(s0), p1 = unpk(s1);
        float part = (p0.x + p0.y) + (p1.x + p1.y);
        part += __shfl_xor_sync(0xffffffffu, part, 16);
        float v = part * ee;
        if ((t & 15) == 0) {
            float vmax = bmax256(v, red);
            if (half == 0) a_sh[cur ^ 1][j] = v * (1.f / vmax);
            off += emx + __logf(vmax);
        } else {
            if (half == 0) a_sh[cur ^ 1][j] = v * 0.0078125f;
            off += emx + LOG128;
        }
        cur ^= 1;
        __syncthreads();
    }

    float term = (half == 0) ? a_sh[cur][j] * __expf(endv[j]) : 0.f;
    float ssum = bsum256(term, red);
    if (tt == 0) g_part[b] = off + __logf(ssum);
}

// ---------------- gold-path score (em reconstructed from eem/emmax) ----------------
__global__ void k_score(const int* __restrict__ tags, const float* __restrict__ trans,
                        const float* __restrict__ startv, const float* __restrict__ endv) {
    int gw = (blockIdx.x * blockDim.x + threadIdx.x) >> 5;
    int lane = threadIdx.x & 31;
    if (gw >= Bc) return;
    int b = gw;
    int len = g_len[b];
    float s = 0.f;
    for (int t = 1 + lane; t < len; t += 32) {
        int tp  = tags[b * Tc + t - 1];
        int tcu = tags[b * Tc + t];
        float em = g_emmax[b * Tc + t] + __logf(g_eem[((size_t)b * Tc + t) * Vc + tcu]);
        s += trans[tp * Vc + tcu] + em;
    }
#pragma unroll
    for (int o = 16; o; o >>= 1) s += __shfl_xor_sync(0xffffffffu, s, o);
    if (lane == 0) {
        int t0 = tags[b * Tc];
        int tl = tags[b * Tc + len - 1];
        float em0 = g_emmax[b * Tc] + __logf(g_eem[(size_t)b * Tc * Vc + t0]);
        s += startv[t0] + em0 + endv[tl];
        g_scorev[b] = s;
    }
}

// ---------------- final reduction ----------------
__global__ void k_final(float* __restrict__ out) {
    __shared__ float red[512];
    int t = threadIdx.x;
    red[t] = g_scorev[t] - g_part[t];
    __syncthreads();
    for (int s = 256; s; s >>= 1) {
        if (t < s) red[t] += red[t + s];
        __syncthreads();
    }
    if (t == 0) out[0] = -red[0] * (1.f / Bc);
}

// ---------------- host launcher ----------------
extern "C" void kernel_launch(void* const* d_in, const int* in_sizes, int n_in,
                              void* d_out, int out_size) {
    const int*   x        = (const int*)d_in[0];
    const int*   tags     = (const int*)d_in[1];
    const float* emb      = (const float*)d_in[2];
    const float* w_ih_l0  = (const float*)d_in[3];
    const float* w_hh_l0  = (const float*)d_in[4];
    const float* b_ih_l0  = (const float*)d_in[5];
    const float* b_hh_l0  = (const float*)d_in[6];
    const float* w_ih_l0r = (const float*)d_in[7];
    const float* w_hh_l0r = (const float*)d_in[8];
    const float* b_ih_l0r = (const float*)d_in[9];
    const float* b_hh_l0r = (const float*)d_in[10];
    const float* w_ih_l1  = (const float*)d_in[11];
    const float* w_hh_l1  = (const float*)d_in[12];
    const float* b_ih_l1  = (const float*)d_in[13];
    const float* b_hh_l1  = (const float*)d_in[14];
    const float* w_ih_l1r = (const float*)d_in[15];
    const float* w_hh_l1r = (const float*)d_in[16];
    const float* b_ih_l1r = (const float*)d_in[17];
    const float* b_hh_l1r = (const float*)d_in[18];
    const float* lin_w    = (const float*)d_in[19];
    const float* lin_b    = (const float*)d_in[20];
    const float* crf_start = (const float*)d_in[21];
    const float* crf_end   = (const float*)d_in[22];
    const float* crf_trans = (const float*)d_in[23];
    float* out = (float*)d_out;

    __nv_bfloat16 *phs0, *phs1, *pw0f, *pw0b, *pw1f, *pw1b, *plw;
    float *ppf, *ppb, *pdm;
    cudaGetSymbolAddress((void**)&ppf,  g_pre_f);
    cudaGetSymbolAddress((void**)&ppb,  g_pre_b);
    cudaGetSymbolAddress((void**)&phs0, g_hs0b);
    cudaGetSymbolAddress((void**)&phs1, g_hs1b);
    cudaGetSymbolAddress((void**)&pdm,  g_dummy);
    cudaGetSymbolAddress((void**)&pw0f, g_wih0f);
    cudaGetSymbolAddress((void**)&pw0b, g_wih0b);
    cudaGetSymbolAddress((void**)&pw1f, g_wih1f);
    cudaGetSymbolAddress((void**)&pw1b, g_wih1b);
    cudaGetSymbolAddress((void**)&plw,  g_linwb);

    const int SM64  = 2 * 128 * 64 * 2;    // 32KB
    const int SM128 = 2 * 128 * 128 * 2;   // 64KB
    cudaFuncSetAttribute((const void*)k_mma<64, false, true>,
                         cudaFuncAttributeMaxDynamicSharedMemorySize, SM64);
    cudaFuncSetAttribute((const void*)k_mma<128, false, false>,
                         cudaFuncAttributeMaxDynamicSharedMemorySize, SM128);
    cudaFuncSetAttribute((const void*)k_mma<128, true, false>,
                         cudaFuncAttributeMaxDynamicSharedMemorySize, SM128);

    const int NROW = Bc * Tc;  // 131072
    const int NT = NROW / 128; // 1024 tiles

    // fused prep: weight cvt + lengths + exp(trans)^T (one launch)
    k_prep1<<<448 + Bc + 64, 256>>>(w_ih_l0, w_ih_l0r, w_ih_l1, w_ih_l1r, lin_w,
                                    x, crf_trans);

    // layer 0 pre-activations (K=64, Gout=256): embedding gathered in-GEMM
    k_mma<64, false, true><<<dim3(NT, 2, 2), 256, SM64>>>(
        nullptr, x, emb, pw0f, pw0b,
        b_ih_l0, b_ih_l0r, b_hh_l0, b_hh_l0r, ppf, ppb, Gc);
    k_lstm<<<dim3(Bc / Mb, 2), 128>>>(ppf, ppb, w_hh_l0, w_hh_l0r, phs0);

    // layer 1 pre-activations (K=128, Gout=256): fwd+bwd fused
    k_mma<128, false, false><<<dim3(NT, 2, 2), 256, SM128>>>(
        phs0, nullptr, nullptr, pw1f, pw1b,
        b_ih_l1, b_ih_l1r, b_hh_l1, b_hh_l1r, ppf, ppb, Gc);
    k_lstm<<<dim3(Bc / Mb, 2), 128>>>(ppf, ppb, w_hh_l1, w_hh_l1r, phs1);

    // emissions (K=128, Gout=128): writes only eem/emmax
    k_mma<128, true, false><<<dim3(NT, 1, 1), 256, SM128>>>(
        phs1, nullptr, nullptr, plw, plw,
        lin_b, lin_b, nullptr, nullptr, pdm, pdm, Vc);

    // CRF (M in registers)
    k_crf<<<Bc, 256>>>(crf_start, crf_end);
    k_score<<<Bc / 8, 256>>>(tags, crf_trans, crf_start, crf_end);
    k_final<<<1, 512>>>(out);
}